// round 8
// baseline (speedup 1.0000x reference)
#include <cuda_runtime.h>
#include <cuda_fp16.h>
#include <math.h>
#include <stdint.h>

// ---------------- problem constants ----------------
#define S     2048
#define HID   2560
#define NH    8
#define NKV   4
#define DH    256
#define WIN   1024
#define QN    (NH*DH)    // 2048
#define KVN   (NKV*DH)   // 1024

// ---------------- scratch ----------------
__device__ float g_q[S * QN];
__device__ float g_k[S * KVN];
__device__ float g_v[S * KVN];
__device__ float g_attn[S * QN];

// int8 quantized operands (2-term splits) + scales
__device__ int8_t g_hs1[S * HID],  g_hs2[S * HID];
__device__ float  g_s_hs[S];
__device__ int8_t g_wq1[QN * HID],  g_wq2[QN * HID];   // transposed [QN][HID]
__device__ float  g_t_wq[QN];
__device__ int8_t g_wk1[KVN * HID], g_wk2[KVN * HID];  // [KVN][HID]
__device__ float  g_t_wk[KVN];
__device__ int8_t g_wv1[KVN * HID], g_wv2[KVN * HID];
__device__ float  g_t_wv[KVN];
__device__ int8_t g_wo1[HID * QN],  g_wo2[HID * QN];   // [HID][QN]
__device__ float  g_t_wo[HID];
__device__ int8_t g_at1[S * QN],    g_at2[S * QN];
__device__ float  g_s_at[S];

// fp16 attention operands (post norm+rope)
__device__ __half g_qh[S * QN],  g_ql[S * QN];
__device__ __half g_kh[S * KVN], g_kl[S * KVN];
__device__ __half g_vh[S * KVN];

// ---------------- PTX helpers ----------------
#define CP16(dst_u32, src_ptr) \
    asm volatile("cp.async.cg.shared.global [%0], [%1], 16;\n" :: "r"(dst_u32), "l"(src_ptr))
#define CP_COMMIT()  asm volatile("cp.async.commit_group;\n")
#define CP_WAIT0()   asm volatile("cp.async.wait_group 0;\n" ::: "memory")

#define LDSM4(R, addr) \
    asm volatile("ldmatrix.sync.aligned.m8n8.x4.shared.b16 {%0,%1,%2,%3}, [%4];\n" \
        : "=r"((R)[0]), "=r"((R)[1]), "=r"((R)[2]), "=r"((R)[3]) : "r"(addr))
#define LDSM4T(R, addr) \
    asm volatile("ldmatrix.sync.aligned.m8n8.x4.trans.shared.b16 {%0,%1,%2,%3}, [%4];\n" \
        : "=r"((R)[0]), "=r"((R)[1]), "=r"((R)[2]), "=r"((R)[3]) : "r"(addr))

#define MMA_FP16(d, a, b0, b1) \
    asm volatile("mma.sync.aligned.m16n8k16.row.col.f32.f16.f16.f32 " \
        "{%0,%1,%2,%3},{%4,%5,%6,%7},{%8,%9},{%0,%1,%2,%3};\n" \
        : "+f"((d)[0]), "+f"((d)[1]), "+f"((d)[2]), "+f"((d)[3]) \
        : "r"((a)[0]), "r"((a)[1]), "r"((a)[2]), "r"((a)[3]), "r"(b0), "r"(b1))

#define MMA_F16A(d, a, b0, b1) \
    asm volatile("mma.sync.aligned.m16n8k16.row.col.f16.f16.f16.f16 " \
        "{%0,%1},{%2,%3,%4,%5},{%6,%7},{%0,%1};\n" \
        : "+r"((d)[0]), "+r"((d)[1]) \
        : "r"((a)[0]), "r"((a)[1]), "r"((a)[2]), "r"((a)[3]), "r"(b0), "r"(b1))

// int8 MMA, s32 accumulate, K=32 per instruction (2x MAC density of f16 k16)
#define MMA_S8(d, a, b0, b1) \
    asm volatile("mma.sync.aligned.m16n8k32.row.col.s32.s8.s8.s32 " \
        "{%0,%1,%2,%3},{%4,%5,%6,%7},{%8,%9},{%0,%1,%2,%3};\n" \
        : "+r"((d)[0]), "+r"((d)[1]), "+r"((d)[2]), "+r"((d)[3]) \
        : "r"((a)[0]), "r"((a)[1]), "r"((a)[2]), "r"((a)[3]), "r"(b0), "r"(b1))

__device__ __forceinline__ uint32_t smem_u32(const void* p) {
    return (uint32_t)__cvta_generic_to_shared(p);
}
__device__ __forceinline__ void add_h2(float* f01, uint32_t packed) {
    __half2 h = *(__half2*)&packed;
    float2 v = __half22float2(h);
    f01[0] += v.x; f01[1] += v.y;
}

// =====================================================================
// row quantization: per-row scale, 2-term int8 split
// =====================================================================
__global__ __launch_bounds__(256) void rowquant_kernel(
    const float* __restrict__ x, int8_t* __restrict__ q1,
    int8_t* __restrict__ q2, float* __restrict__ s, int K)
{
    const int row = blockIdx.x;
    const int t = threadIdx.x;
    const float* r = x + (size_t)row * K;

    float mx = 0.f;
    for (int k = t; k < K; k += 256) mx = fmaxf(mx, fabsf(r[k]));
#pragma unroll
    for (int o = 16; o; o >>= 1) mx = fmaxf(mx, __shfl_xor_sync(0xffffffffu, mx, o));
    __shared__ float wmax[8];
    if ((t & 31) == 0) wmax[t >> 5] = mx;
    __syncthreads();
    float m2 = 0.f;
#pragma unroll
    for (int i = 0; i < 8; i++) m2 = fmaxf(m2, wmax[i]);

    float scale = fmaxf(m2, 1e-20f) * (1.f / 127.f);
    if (t == 0) s[row] = scale;
    float inv = 1.f / scale;

    for (int k = t; k < K; k += 256) {
        float v = r[k];
        int a = __float2int_rn(v * inv);
        a = max(-127, min(127, a));
        float res = v - (float)a * scale;
        int b = __float2int_rn(res * inv * 128.f);
        q1[(size_t)row * K + k] = (int8_t)a;
        q2[(size_t)row * K + k] = (int8_t)b;
    }
}

// per-column max of W[K,N]
__global__ __launch_bounds__(256) void colmax_kernel(
    const float* __restrict__ W, float* __restrict__ tB, int K, int N)
{
    int n = blockIdx.x * 256 + threadIdx.x;
    if (n >= N) return;
    float mx = 0.f;
    for (int k = 0; k < K; k++) mx = fmaxf(mx, fabsf(W[(size_t)k * N + n]));
    tB[n] = fmaxf(mx, 1e-20f) * (1.f / 127.f);
}

// quantize + transpose: W[K,N] -> q1,q2 [N,K] int8
__global__ __launch_bounds__(256) void quantT_kernel(
    const float* __restrict__ W, const float* __restrict__ tB,
    int8_t* __restrict__ q1, int8_t* __restrict__ q2, int K, int N)
{
    __shared__ float tile[32][33];
    const int nb = blockIdx.x * 32;
    const int kb = blockIdx.y * 32;
    const int tx = threadIdx.x & 31;
    const int ty = threadIdx.x >> 5;   // 0..7
#pragma unroll
    for (int i = 0; i < 4; i++)
        tile[ty + i * 8][tx] = W[(size_t)(kb + ty + i * 8) * N + nb + tx];
    __syncthreads();
#pragma unroll
    for (int i = 0; i < 4; i++) {
        int n = nb + ty + i * 8;
        int k = kb + tx;
        float v = tile[tx][ty + i * 8];
        float scale = tB[n];
        float inv = 1.f / scale;
        int a = __float2int_rn(v * inv);
        a = max(-127, min(127, a));
        float res = v - (float)a * scale;
        int b = __float2int_rn(res * inv * 128.f);
        q1[(size_t)n * K + k] = (int8_t)a;
        q2[(size_t)n * K + k] = (int8_t)b;
    }
}

// =====================================================================
// int8 tensor-core GEMM (3 IMMA passes = exact a1b1 + cross terms)
// C[M,N] = sA_i * tB_j * (P1 + P23/128).  B given transposed [N,K].
// 128x128x64 CTA tile, 8 warps (2x4), warp tile 64x32.
// =====================================================================
#define QROW   80                      // bytes per 64-int8 row (16B pad)
#define QOP    (128 * QROW)            // 10240 B per operand tile
#define QSTAGE (4 * QOP)               // 40960 B
#define GI8_SMEM (2 * QSTAGE)          // 81920 B

__global__ __launch_bounds__(256) void gemm_i8_kernel(
    const int8_t* __restrict__ A1, const int8_t* __restrict__ A2,
    const int8_t* __restrict__ B1, const int8_t* __restrict__ B2,
    const float* __restrict__ sA, const float* __restrict__ tB,
    float* __restrict__ C, int M, int N, int K)
{
    extern __shared__ char smq[];
    const int t    = threadIdx.x;
    const int lane = t & 31;
    const int wid  = t >> 5;
    const int wm   = wid >> 2;
    const int wn   = wid & 3;
    const int m0   = blockIdx.y * 128;
    const int n0   = blockIdx.x * 128;

    int acc1[4][4][4], acc2[4][4][4];
#pragma unroll
    for (int mi = 0; mi < 4; mi++)
#pragma unroll
        for (int ni = 0; ni < 4; ni++)
#pragma unroll
            for (int r = 0; r < 4; r++) { acc1[mi][ni][r] = 0; acc2[mi][ni][r] = 0; }

    uint32_t sb[2][4];
#pragma unroll
    for (int b = 0; b < 2; b++) {
        uint32_t base = smem_u32(smq) + b * QSTAGE;
        sb[b][0] = base;            // A1
        sb[b][1] = base + QOP;      // A2
        sb[b][2] = base + 2 * QOP;  // B1
        sb[b][3] = base + 3 * QOP;  // B2
    }

    auto issue = [&](int k0, int buf) {
#pragma unroll
        for (int p = 0; p < 2; p++) {
            int id = t + p * 256;
            int row = id >> 2, seg = id & 3;
            uint32_t d = (uint32_t)(row * QROW + seg * 16);
            size_t ga = (size_t)(m0 + row) * K + k0 + seg * 16;
            size_t gb = (size_t)(n0 + row) * K + k0 + seg * 16;
            CP16(sb[buf][0] + d, A1 + ga);
            CP16(sb[buf][1] + d, A2 + ga);
            CP16(sb[buf][2] + d, B1 + gb);
            CP16(sb[buf][3] + d, B2 + gb);
        }
        CP_COMMIT();
    };

    issue(0, 0);
    const int nIter = K / 64;

    for (int it = 0; it < nIter; it++) {
        CP_WAIT0();
        __syncthreads();
        if (it + 1 < nIter) issue((it + 1) * 64, (it + 1) & 1);

        const int buf = it & 1;
        const uint32_t a1s = sb[buf][0], a2s = sb[buf][1];
        const uint32_t b1s = sb[buf][2], b2s = sb[buf][3];

#pragma unroll
        for (int ks = 0; ks < 2; ks++) {
            const uint32_t colb = (uint32_t)(ks * 32 + ((lane >> 4) & 1) * 16);
            uint32_t fa1[4][4], fa2[4][4], fb1[2][4], fb2[2][4];
#pragma unroll
            for (int mi = 0; mi < 4; mi++) {
                uint32_t off = (uint32_t)((wm * 64 + mi * 16 + (lane & 15)) * QROW) + colb;
                LDSM4(fa1[mi], a1s + off);
                LDSM4(fa2[mi], a2s + off);
            }
#pragma unroll
            for (int np = 0; np < 2; np++) {
                uint32_t off = (uint32_t)((wn * 32 + np * 16 + (lane & 15)) * QROW) + colb;
                LDSM4(fb1[np], b1s + off);
                LDSM4(fb2[np], b2s + off);
            }
#pragma unroll
            for (int mi = 0; mi < 4; mi++)
#pragma unroll
                for (int ni = 0; ni < 4; ni++) {
                    int np = ni >> 1, sl = ni & 1;
                    MMA_S8(acc1[mi][ni], fa1[mi], fb1[np][sl], fb1[np][sl + 2]);
                    MMA_S8(acc2[mi][ni], fa1[mi], fb2[np][sl], fb2[np][sl + 2]);
                    MMA_S8(acc2[mi][ni], fa2[mi], fb1[np][sl], fb1[np][sl + 2]);
                }
        }
        __syncthreads();
    }

    const int g  = lane >> 2;
    const int c2 = (lane & 3) * 2;
    const float q = 1.f / 128.f;
#pragma unroll
    for (int mi = 0; mi < 4; mi++) {
        int r0 = m0 + wm * 64 + mi * 16 + g;
        float sa0 = sA[r0], sa1 = sA[r0 + 8];
#pragma unroll
        for (int ni = 0; ni < 4; ni++) {
            int col = n0 + wn * 32 + ni * 8 + c2;
            float tb0 = tB[col], tb1 = tB[col + 1];
            float v00 = sa0 * tb0 * ((float)acc1[mi][ni][0] + (float)acc2[mi][ni][0] * q);
            float v01 = sa0 * tb1 * ((float)acc1[mi][ni][1] + (float)acc2[mi][ni][1] * q);
            float v10 = sa1 * tb0 * ((float)acc1[mi][ni][2] + (float)acc2[mi][ni][2] * q);
            float v11 = sa1 * tb1 * ((float)acc1[mi][ni][3] + (float)acc2[mi][ni][3] * q);
            *(float2*)(C + (size_t)r0 * N + col)       = make_float2(v00, v01);
            *(float2*)(C + (size_t)(r0 + 8) * N + col) = make_float2(v10, v11);
        }
    }
}

// =====================================================================
// Fused RMSNorm (+weight) + RoPE — warp-per-head (unchanged from R7)
// =====================================================================
__global__ __launch_bounds__(256) void norm_rope_kernel(
    const float* __restrict__ q, const float* __restrict__ k, const float* __restrict__ v,
    const float* __restrict__ cosp, const float* __restrict__ sinp,
    const float* __restrict__ qw, const float* __restrict__ kw,
    __half* __restrict__ qh, __half* __restrict__ ql,
    __half* __restrict__ kh, __half* __restrict__ kl,
    __half* __restrict__ vh)
{
    const int lane = threadIdx.x & 31;
    const int row  = blockIdx.x * 8 + (threadIdx.x >> 5);
    const int s    = row >> 4;
    const int idx  = row & 15;

    const float* base;
    const float* w;
    __half *oh, *ol;
    bool rope;
    if (idx < 8) {
        base = q + (size_t)s * QN + idx * DH; w = qw; rope = true;
        oh = qh + (size_t)s * QN + idx * DH; ol = ql + (size_t)s * QN + idx * DH;
    } else if (idx < 12) {
        base = k + (size_t)s * KVN + (idx - 8) * DH; w = kw; rope = true;
        oh = kh + (size_t)s * KVN + (idx - 8) * DH; ol = kl + (size_t)s * KVN + (idx - 8) * DH;
    } else {
        base = v + (size_t)s * KVN + (idx - 12) * DH; w = nullptr; rope = false;
        oh = vh + (size_t)s * KVN + (idx - 12) * DH; ol = nullptr;
    }

    const int d0 = lane * 8;
    float x[8];
    *(float4*)&x[0] = *(const float4*)(base + d0);
    *(float4*)&x[4] = *(const float4*)(base + d0 + 4);

    float ss = 0.f;
#pragma unroll
    for (int j = 0; j < 8; j++) ss += x[j] * x[j];
#pragma unroll
    for (int o = 16; o; o >>= 1) ss += __shfl_xor_sync(0xffffffffu, ss, o);

    float inv = rsqrtf(ss * (1.0f / 256.0f) + 1e-6f);
    float y[8];
#pragma unroll
    for (int j = 0; j < 8; j++) y[j] = x[j] * inv;
    if (w) {
        float wv[8];
        *(float4*)&wv[0] = *(const float4*)(w + d0);
        *(float4*)&wv[4] = *(const float4*)(w + d0 + 4);
#pragma unroll
        for (int j = 0; j < 8; j++) y[j] *= wv[j];
    }

    float out[8];
    if (rope) {
        float c[8], si[8];
        *(float4*)&c[0]  = *(const float4*)(cosp + (size_t)s * DH + d0);
        *(float4*)&c[4]  = *(const float4*)(cosp + (size_t)s * DH + d0 + 4);
        *(float4*)&si[0] = *(const float4*)(sinp + (size_t)s * DH + d0);
        *(float4*)&si[4] = *(const float4*)(sinp + (size_t)s * DH + d0 + 4);
#pragma unroll
        for (int j = 0; j < 8; j++) {
            float pv = __shfl_xor_sync(0xffffffffu, y[j], 16);
            float rh = (lane < 16) ? -pv : pv;
            out[j] = y[j] * c[j] + rh * si[j];
        }
    } else {
#pragma unroll
        for (int j = 0; j < 8; j++) out[j] = y[j];
    }

    __half hi8[8], lo8[8];
#pragma unroll
    for (int j = 0; j < 8; j++) {
        hi8[j] = __float2half_rn(out[j]);
        lo8[j] = __float2half_rn(out[j] - __half2float(hi8[j]));
    }
    *(uint4*)(oh + d0) = *(uint4*)hi8;
    if (ol) *(uint4*)(ol + d0) = *(uint4*)lo8;
}

// =====================================================================
// TC flash attention (R7, epilogue -> fp32 output for int8 requant)
// =====================================================================
#define KT    32
#define ASTR  264
#define ATT_SM_ELEM (2*128*ASTR + 3*KT*ASTR)
#define ATT_SM_BYTES (ATT_SM_ELEM * 2)

__global__ __launch_bounds__(256, 1) void attn_tc_kernel(
    const __half* __restrict__ Qh, const __half* __restrict__ Ql,
    const __half* __restrict__ Kh, const __half* __restrict__ Kl,
    const __half* __restrict__ Vh, float* __restrict__ Og)
{
    extern __shared__ __half sm2[];
    const int t    = threadIdx.x;
    const int lane = t & 31;
    const int w    = t >> 5;
    const int q0   = blockIdx.x * 128;
    const int h    = blockIdx.y;
    const int kvh  = h >> 1;

    const uint32_t sQh = smem_u32(sm2);
    const uint32_t sQl = sQh + 128 * ASTR * 2;
    const uint32_t sKh = sQl + 128 * ASTR * 2;
    const uint32_t sKl = sKh + KT * ASTR * 2;
    const uint32_t sVh = sKl + KT * ASTR * 2;

    const __half* gqh = Qh + (size_t)q0 * QN + h * DH;
    const __half* gql = Ql + (size_t)q0 * QN + h * DH;
#pragma unroll
    for (int it = 0; it < 16; it++) {
        int id = t + it * 256;
        int row = id >> 5, ch = id & 31;
        uint32_t d = (uint32_t)(row * ASTR + ch * 8) * 2;
        size_t g = (size_t)row * QN + ch * 8;
        CP16(sQh + d, gqh + g);
        CP16(sQl + d, gql + g);
    }
    CP_COMMIT();

    float o[32][4];
#pragma unroll
    for (int dt = 0; dt < 32; dt++)
#pragma unroll
        for (int r = 0; r < 4; r++) o[dt][r] = 0.f;
    float mrow[2] = {-1e30f, -1e30f};
    float lrow[2] = {0.f, 0.f};

    CP_WAIT0();
    __syncthreads();

    const int kb_lo = max(0, q0 - (WIN - 1)) >> 5;
    const int kb_hi = (q0 + 127) >> 5;
    const int qw_lo = q0 + w * 16;
    const int gq_row = lane >> 2;
    const int t4 = lane & 3;

    for (int kb = kb_lo; kb <= kb_hi; kb++) {
        const int k0 = kb * KT;
        __syncthreads();

        {
            const __half* gkh = Kh + (size_t)k0 * KVN + kvh * DH;
            const __half* gkl = Kl + (size_t)k0 * KVN + kvh * DH;
            const __half* gvh = Vh + (size_t)k0 * KVN + kvh * DH;
#pragma unroll
            for (int it = 0; it < 4; it++) {
                int id = t + it * 256;
                int row = id >> 5, ch = id & 31;
                uint32_t d = (uint32_t)(row * ASTR + ch * 8) * 2;
                size_t g = (size_t)row * KVN + ch * 8;
                CP16(sKh + d, gkh + g);
                CP16(sKl + d, gkl + g);
                CP16(sVh + d, gvh + g);
            }
        }
        CP_COMMIT();
        CP_WAIT0();
        __syncthreads();

        bool active = (k0 <= qw_lo + 15) && (k0 + KT - 1 >= qw_lo - (WIN - 1));
        if (!active) continue;

        float s[4][4];
        uint32_t sl[4][2];
#pragma unroll
        for (int tl = 0; tl < 4; tl++) {
#pragma unroll
            for (int r = 0; r < 4; r++) s[tl][r] = 0.f;
            sl[tl][0] = 0u; sl[tl][1] = 0u;
        }

#pragma unroll
        for (int dc = 0; dc < 16; dc++) {
            uint32_t qa[4], qb[4], k1h[4], k2h[4], k1l[4], k2l[4];
            uint32_t qoff = (uint32_t)((w * 16 + (lane & 15)) * ASTR + dc * 16 + (lane >> 4) * 8) * 2;
            LDSM4(qa, sQh + qoff);
            LDSM4(qb, sQl + qoff);
            uint32_t koff = (uint32_t)((lane & 15) * ASTR + dc * 16 + (lane >> 4) * 8) * 2;
            LDSM4(k1h, sKh + koff);
            LDSM4(k2h, sKh + koff + 16 * ASTR * 2);
            LDSM4(k1l, sKl + koff);
            LDSM4(k2l, sKl + koff + 16 * ASTR * 2);

            MMA_FP16(s[0], qa, k1h[0], k1h[2]);
            MMA_FP16(s[1], qa, k1h[1], k1h[3]);
            MMA_FP16(s[2], qa, k2h[0], k2h[2]);
            MMA_FP16(s[3], qa, k2h[1], k2h[3]);
            MMA_F16A(sl[0], qa, k1l[0], k1l[2]);
            MMA_F16A(sl[1], qa, k1l[1], k1l[3]);
            MMA_F16A(sl[2], qa, k2l[0], k2l[2]);
            MMA_F16A(sl[3], qa, k2l[1], k2l[3]);
            MMA_F16A(sl[0], qb, k1h[0], k1h[2]);
            MMA_F16A(sl[1], qb, k1h[1], k1h[3]);
            MMA_F16A(sl[2], qb, k2h[0], k2h[2]);
            MMA_F16A(sl[3], qb, k2h[1], k2h[3]);
        }
#pragma unroll
        for (int tl = 0; tl < 4; tl++) {
            add_h2(&s[tl][0], sl[tl][0]);
            add_h2(&s[tl][2], sl[tl][1]);
        }

        float corr[2];
#pragma unroll
        for (int r = 0; r < 2; r++) {
            int qg = qw_lo + gq_row + r * 8;
            float mx = -1e30f;
#pragma unroll
            for (int tl = 0; tl < 4; tl++) {
#pragma unroll
                for (int c = 0; c < 2; c++) {
                    int kg = k0 + tl * 8 + 2 * t4 + c;
                    bool ok = (kg <= qg) && (qg - kg < WIN);
                    if (!ok) s[tl][r * 2 + c] = -1e30f;
                    mx = fmaxf(mx, s[tl][r * 2 + c]);
                }
            }
            mx = fmaxf(mx, __shfl_xor_sync(0xffffffffu, mx, 1));
            mx = fmaxf(mx, __shfl_xor_sync(0xffffffffu, mx, 2));
            float m_new = fmaxf(mrow[r], mx);
            float mexp = (m_new <= -1e29f) ? 0.f : m_new;
            float sum = 0.f;
#pragma unroll
            for (int tl = 0; tl < 4; tl++) {
#pragma unroll
                for (int c = 0; c < 2; c++) {
                    float p = __expf(s[tl][r * 2 + c] - mexp);
                    s[tl][r * 2 + c] = p;
                    sum += p;
                }
            }
            sum += __shfl_xor_sync(0xffffffffu, sum, 1);
            sum += __shfl_xor_sync(0xffffffffu, sum, 2);
            corr[r] = __expf(mrow[r] - m_new);
            mrow[r] = m_new;
            lrow[r] = lrow[r] * corr[r] + sum;
        }

        uint32_t ph[2][4], pl[2][4];
#pragma unroll
        for (int kc = 0; kc < 2; kc++) {
#pragma unroll
            for (int r2 = 0; r2 < 4; r2++) {
                int tl = kc * 2 + (r2 >> 1);
                int r  = r2 & 1;
                float p0 = s[tl][r * 2 + 0];
                float p1 = s[tl][r * 2 + 1];
                __half h0 = __float2half_rn(p0);
                __half h1 = __float2half_rn(p1);
                __half2 hh = __halves2half2(h0, h1);
                __half2 ll = __halves2half2(__float2half_rn(p0 - __half2float(h0)),
                                            __float2half_rn(p1 - __half2float(h1)));
                ph[kc][r2] = *(uint32_t*)&hh;
                pl[kc][r2] = *(uint32_t*)&ll;
            }
        }

#pragma unroll
        for (int dt = 0; dt < 32; dt++) {
            o[dt][0] *= corr[0]; o[dt][1] *= corr[0];
            o[dt][2] *= corr[1]; o[dt][3] *= corr[1];
        }

#pragma unroll
        for (int dg = 0; dg < 16; dg++) {
#pragma unroll
            for (int kc = 0; kc < 2; kc++) {
                uint32_t vh4[4];
                uint32_t voff = (uint32_t)((kc * 16 + (lane & 7) + ((lane >> 3) & 1) * 8) * ASTR
                                           + dg * 16 + ((lane >> 4) & 1) * 8) * 2;
                LDSM4T(vh4, sVh + voff);
                MMA_FP16(o[2 * dg],     ph[kc], vh4[0], vh4[1]);
                MMA_FP16(o[2 * dg + 1], ph[kc], vh4[2], vh4[3]);
                MMA_FP16(o[2 * dg],     pl[kc], vh4[0], vh4[1]);
                MMA_FP16(o[2 * dg + 1], pl[kc], vh4[2], vh4[3]);
            }
        }
    }

    float inv0 = 1.f / lrow[0];
    float inv1 = 1.f / lrow[1];
    float* dst0 = Og + (size_t)(q0 + w * 16 + gq_row) * QN + h * DH;
    float* dst1 = dst0 + (size_t)8 * QN;
#pragma unroll
    for (int dt = 0; dt < 32; dt++) {
        int col = dt * 8 + 2 * t4;
        *(float2*)(dst0 + col) = make_float2(o[dt][0] * inv0, o[dt][1] * inv0);
        *(float2*)(dst1 + col) = make_float2(o[dt][2] * inv1, o[dt][3] * inv1);
    }
}

// =====================================================================
// kernel_launch
// =====================================================================
extern "C" void kernel_launch(void* const* d_in, const int* in_sizes, int n_in,
                              void* d_out, int out_size)
{
    const float* hs   = (const float*)d_in[0];
    const float* cosp = (const float*)d_in[1];
    const float* sinp = (const float*)d_in[2];
    const float* wq   = (const float*)d_in[3];
    const float* wk   = (const float*)d_in[4];
    const float* wv   = (const float*)d_in[5];
    const float* wo   = (const float*)d_in[6];
    const float* qw   = (const float*)d_in[7];
    const float* kw   = (const float*)d_in[8];
    float* out = (float*)d_out;

    float *gq, *gk, *gv, *ga;
    cudaGetSymbolAddress((void**)&gq, g_q);
    cudaGetSymbolAddress((void**)&gk, g_k);
    cudaGetSymbolAddress((void**)&gv, g_v);
    cudaGetSymbolAddress((void**)&ga, g_attn);

    int8_t *hs1, *hs2, *wq1, *wq2, *wk1, *wk2, *wv1, *wv2, *wo1, *wo2, *at1, *at2;
    float *s_hs, *t_wq, *t_wk, *t_wv, *t_wo, *s_at;
    cudaGetSymbolAddress((void**)&hs1, g_hs1); cudaGetSymbolAddress((void**)&hs2, g_hs2);
    cudaGetSymbolAddress((void**)&wq1, g_wq1); cudaGetSymbolAddress((void**)&wq2, g_wq2);
    cudaGetSymbolAddress((void**)&wk1, g_wk1); cudaGetSymbolAddress((void**)&wk2, g_wk2);
    cudaGetSymbolAddress((void**)&wv1, g_wv1); cudaGetSymbolAddress((void**)&wv2, g_wv2);
    cudaGetSymbolAddress((void**)&wo1, g_wo1); cudaGetSymbolAddress((void**)&wo2, g_wo2);
    cudaGetSymbolAddress((void**)&at1, g_at1); cudaGetSymbolAddress((void**)&at2, g_at2);
    cudaGetSymbolAddress((void**)&s_hs, g_s_hs); cudaGetSymbolAddress((void**)&t_wq, g_t_wq);
    cudaGetSymbolAddress((void**)&t_wk, g_t_wk); cudaGetSymbolAddress((void**)&t_wv, g_t_wv);
    cudaGetSymbolAddress((void**)&t_wo, g_t_wo); cudaGetSymbolAddress((void**)&s_at, g_s_at);

    __half *qh, *ql, *kh, *kl, *vh;
    cudaGetSymbolAddress((void**)&qh, g_qh); cudaGetSymbolAddress((void**)&ql, g_ql);
    cudaGetSymbolAddress((void**)&kh, g_kh); cudaGetSymbolAddress((void**)&kl, g_kl);
    cudaGetSymbolAddress((void**)&vh, g_vh);

    cudaFuncSetAttribute(gemm_i8_kernel, cudaFuncAttributeMaxDynamicSharedMemorySize,
                         GI8_SMEM);
    cudaFuncSetAttribute(attn_tc_kernel, cudaFuncAttributeMaxDynamicSharedMemorySize,
                         ATT_SM_BYTES);

    // quantize activations + weights
    rowquant_kernel<<<S, 256>>>(hs, hs1, hs2, s_hs, HID);
    colmax_kernel<<<QN / 256, 256>>>(wq, t_wq, HID, QN);
    colmax_kernel<<<KVN / 256, 256>>>(wk, t_wk, HID, KVN);
    colmax_kernel<<<KVN / 256, 256>>>(wv, t_wv, HID, KVN);
    colmax_kernel<<<HID / 256, 256>>>(wo, t_wo, QN, HID);
    quantT_kernel<<<dim3(QN / 32,  HID / 32), 256>>>(wq, t_wq, wq1, wq2, HID, QN);
    quantT_kernel<<<dim3(KVN / 32, HID / 32), 256>>>(wk, t_wk, wk1, wk2, HID, KVN);
    quantT_kernel<<<dim3(KVN / 32, HID / 32), 256>>>(wv, t_wv, wv1, wv2, HID, KVN);
    quantT_kernel<<<dim3(HID / 32, QN / 32), 256>>>(wo, t_wo, wo1, wo2, QN, HID);

    // QKV projections on int8 tensor cores
    gemm_i8_kernel<<<dim3(QN / 128,  S / 128), 256, GI8_SMEM>>>(
        hs1, hs2, wq1, wq2, s_hs, t_wq, gq, S, QN, HID);
    gemm_i8_kernel<<<dim3(KVN / 128, S / 128), 256, GI8_SMEM>>>(
        hs1, hs2, wk1, wk2, s_hs, t_wk, gk, S, KVN, HID);
    gemm_i8_kernel<<<dim3(KVN / 128, S / 128), 256, GI8_SMEM>>>(
        hs1, hs2, wv1, wv2, s_hs, t_wv, gv, S, KVN, HID);

    // RMSNorm + RoPE -> fp16 attention operands
    norm_rope_kernel<<<S * 16 / 8, 256>>>(gq, gk, gv, cosp, sinp, qw, kw,
                                          qh, ql, kh, kl, vh);

    // attention (fp16 TC, fp32 out)
    attn_tc_kernel<<<dim3(S / 128, NH), 256, ATT_SM_BYTES>>>(
        qh, ql, kh, kl, vh, ga);

    // quantize attention output, then int8 output projection
    rowquant_kernel<<<S, 256>>>(ga, at1, at2, s_at, QN);
    gemm_i8_kernel<<<dim3(HID / 128, S / 128), 256, GI8_SMEM>>>(
        at1, at2, wo1, wo2, s_at, t_wo, out, S, HID, QN);
}

// round 9
// speedup vs baseline: 3.2590x; 3.2590x over previous
#include <cuda_runtime.h>
#include <cuda_fp16.h>
#include <math.h>
#include <stdint.h>

// ---------------- problem constants ----------------
#define S     2048
#define HID   2560
#define NH    8
#define NKV   4
#define DH    256
#define WIN   1024
#define QN    (NH*DH)    // 2048
#define KVN   (NKV*DH)   // 1024

// ---------------- scratch ----------------
__device__ float g_q[S * QN];
__device__ float g_k[S * KVN];
__device__ float g_v[S * KVN];

__device__ __half g_hs_h[S * HID],  g_hs_l[S * HID];
__device__ __half g_wq_h[HID * QN], g_wq_l[HID * QN];
__device__ __half g_wk_h[HID * KVN], g_wk_l[HID * KVN];
__device__ __half g_wv_h[HID * KVN];
__device__ __half g_wo_h[QN * HID];
__device__ __half g_at_h[S * QN],   g_at_l[S * QN];

__device__ __half g_qh[S * QN],  g_ql[S * QN];
__device__ __half g_kh[S * KVN], g_kl[S * KVN];
__device__ __half g_vh[S * KVN];

// ---------------- PTX helpers ----------------
#define CP16(dst_u32, src_ptr) \
    asm volatile("cp.async.cg.shared.global [%0], [%1], 16;\n" :: "r"(dst_u32), "l"(src_ptr))
#define CP_COMMIT()  asm volatile("cp.async.commit_group;\n")
#define CP_WAIT0()   asm volatile("cp.async.wait_group 0;\n" ::: "memory")
#define CP_WAIT1()   asm volatile("cp.async.wait_group 1;\n" ::: "memory")

#define LDSM4(R, addr) \
    asm volatile("ldmatrix.sync.aligned.m8n8.x4.shared.b16 {%0,%1,%2,%3}, [%4];\n" \
        : "=r"((R)[0]), "=r"((R)[1]), "=r"((R)[2]), "=r"((R)[3]) : "r"(addr))
#define LDSM4T(R, addr) \
    asm volatile("ldmatrix.sync.aligned.m8n8.x4.trans.shared.b16 {%0,%1,%2,%3}, [%4];\n" \
        : "=r"((R)[0]), "=r"((R)[1]), "=r"((R)[2]), "=r"((R)[3]) : "r"(addr))

#define MMA_FP16(d, a, b0, b1) \
    asm volatile("mma.sync.aligned.m16n8k16.row.col.f32.f16.f16.f32 " \
        "{%0,%1,%2,%3},{%4,%5,%6,%7},{%8,%9},{%0,%1,%2,%3};\n" \
        : "+f"((d)[0]), "+f"((d)[1]), "+f"((d)[2]), "+f"((d)[3]) \
        : "r"((a)[0]), "r"((a)[1]), "r"((a)[2]), "r"((a)[3]), "r"(b0), "r"(b1))

#define MMA_F16A(d, a, b0, b1) \
    asm volatile("mma.sync.aligned.m16n8k16.row.col.f16.f16.f16.f16 " \
        "{%0,%1},{%2,%3,%4,%5},{%6,%7},{%0,%1};\n" \
        : "+r"((d)[0]), "+r"((d)[1]) \
        : "r"((a)[0]), "r"((a)[1]), "r"((a)[2]), "r"((a)[3]), "r"(b0), "r"(b1))

__device__ __forceinline__ uint32_t smem_u32(const void* p) {
    return (uint32_t)__cvta_generic_to_shared(p);
}
__device__ __forceinline__ void add_h2(float* f01, uint32_t packed) {
    __half2 h = *(__half2*)&packed;
    float2 v = __half22float2(h);
    f01[0] += v.x; f01[1] += v.y;
}
// XOR swizzle for 512B rows: 16B chunk cb permuted by row low bits
__device__ __forceinline__ uint32_t swz(int row, int cb) {
    return (uint32_t)(row * 512 + ((cb ^ (row & 7)) << 4));
}

// =====================================================================
// Fused split kernel: all hi/lo conversions in ONE launch.
// blocks: [0,5120) hs | [5120,10240) wq | [10240,12800) wk
//         [12800,15360) wv (hi only) | [15360,20480) wo (hi only)
// =====================================================================
__global__ __launch_bounds__(256) void split_all_kernel(
    const float* __restrict__ hs, const float* __restrict__ wq,
    const float* __restrict__ wk, const float* __restrict__ wv,
    const float* __restrict__ wo,
    __half* __restrict__ hsh, __half* __restrict__ hsl,
    __half* __restrict__ wqh, __half* __restrict__ wql,
    __half* __restrict__ wkh, __half* __restrict__ wkl,
    __half* __restrict__ wvh, __half* __restrict__ woh)
{
    int b = blockIdx.x;
    const float* x; __half *h, *l;
    if (b < 5120)       { x = hs; h = hsh; l = hsl; }
    else if (b < 10240) { x = wq; h = wqh; l = wql; b -= 5120; }
    else if (b < 12800) { x = wk; h = wkh; l = wkl; b -= 10240; }
    else if (b < 15360) { x = wv; h = wvh; l = nullptr; b -= 12800; }
    else                { x = wo; h = woh; l = nullptr; b -= 15360; }

    int i = (b * 256 + threadIdx.x) * 4;
    float4 v = *(const float4*)(x + i);
    __half h0 = __float2half_rn(v.x), h1 = __float2half_rn(v.y);
    __half h2 = __float2half_rn(v.z), h3 = __float2half_rn(v.w);
    *(__half2*)(h + i)     = __halves2half2(h0, h1);
    *(__half2*)(h + i + 2) = __halves2half2(h2, h3);
    if (l) {
        *(__half2*)(l + i)     = __halves2half2(
            __float2half_rn(v.x - __half2float(h0)), __float2half_rn(v.y - __half2float(h1)));
        *(__half2*)(l + i + 2) = __halves2half2(
            __float2half_rn(v.z - __half2float(h2)), __float2half_rn(v.w - __half2float(h3)));
    }
}

// =====================================================================
// fp16 TC GEMM body (shared by fused-QKV and wo kernels)
// hi pass f32-acc + cross passes f16-acc. 128x128x32 tile, 8 warps.
// =====================================================================
#define AS_STR 40
#define BS_STR 136
#define ABUF   (128 * AS_STR)
#define BBUF   (32 * BS_STR)
#define BUFELEM (2 * ABUF + 2 * BBUF)
#define GEMM_SMEM_BYTES (2 * BUFELEM * 2)

__device__ __forceinline__ void gemm_body(
    const __half* __restrict__ Ah, const __half* __restrict__ Al,
    const __half* __restrict__ Bh, const __half* __restrict__ Bl,
    float* __restrict__ C, int N, int K, int m0, int n0, int passes,
    __half* smbuf)
{
    const int t    = threadIdx.x;
    const int lane = t & 31;
    const int wid  = t >> 5;
    const int wm   = wid >> 2;
    const int wn   = wid & 3;

    float acc[4][4][4];
    uint32_t accL[4][4][2];
#pragma unroll
    for (int mi = 0; mi < 4; mi++)
#pragma unroll
        for (int ni = 0; ni < 4; ni++) {
#pragma unroll
            for (int r = 0; r < 4; r++) acc[mi][ni][r] = 0.f;
            accL[mi][ni][0] = 0u; accL[mi][ni][1] = 0u;
        }

    uint32_t sbase[2][4];
#pragma unroll
    for (int b = 0; b < 2; b++) {
        __half* p = smbuf + b * BUFELEM;
        sbase[b][0] = smem_u32(p);
        sbase[b][1] = smem_u32(p + ABUF);
        sbase[b][2] = smem_u32(p + 2 * ABUF);
        sbase[b][3] = smem_u32(p + 2 * ABUF + BBUF);
    }

    auto issue = [&](int k0, int buf) {
#pragma unroll
        for (int p = 0; p < 2; p++) {
            int id = t + p * 256;
            int am = id >> 2, ac = (id & 3) * 8;
            size_t aoff = (size_t)(m0 + am) * K + k0 + ac;
            uint32_t ad = (uint32_t)(am * AS_STR + ac) * 2;
            CP16(sbase[buf][0] + ad, Ah + aoff);
            CP16(sbase[buf][1] + ad, Al + aoff);
            int bk = id >> 4, bc = (id & 15) * 8;
            size_t boff = (size_t)(k0 + bk) * N + n0 + bc;
            uint32_t bd = (uint32_t)(bk * BS_STR + bc) * 2;
            CP16(sbase[buf][2] + bd, Bh + boff);
            if (passes == 3) CP16(sbase[buf][3] + bd, Bl + boff);
        }
        CP_COMMIT();
    };

    issue(0, 0);
    const int nIter = K / 32;

    for (int it = 0; it < nIter; it++) {
        CP_WAIT0();
        __syncthreads();
        if (it + 1 < nIter) issue((it + 1) * 32, (it + 1) & 1);

        const int buf = it & 1;
        const uint32_t ah_s = sbase[buf][0];
        const uint32_t al_s = sbase[buf][1];
        const uint32_t bh_s = sbase[buf][2];
        const uint32_t bl_s = sbase[buf][3];

#pragma unroll
        for (int ks = 0; ks < 32; ks += 16) {
            uint32_t fah[4][4], fal[4][4], fbh[2][4], fbl[2][4];

            int arow = lane & 15;
            int acol = ks + ((lane >> 4) & 1) * 8;
#pragma unroll
            for (int mi = 0; mi < 4; mi++) {
                uint32_t off = (uint32_t)((wm * 64 + mi * 16 + arow) * AS_STR + acol) * 2;
                LDSM4(fah[mi], ah_s + off);
                LDSM4(fal[mi], al_s + off);
            }

            int bkrow = ks + (lane & 7) + ((lane >> 3) & 1) * 8;
#pragma unroll
            for (int np = 0; np < 2; np++) {
                int bcol = wn * 32 + np * 16 + ((lane >> 4) & 1) * 8;
                uint32_t off = (uint32_t)(bkrow * BS_STR + bcol) * 2;
                LDSM4T(fbh[np], bh_s + off);
                if (passes == 3) LDSM4T(fbl[np], bl_s + off);
            }

#pragma unroll
            for (int mi = 0; mi < 4; mi++)
#pragma unroll
                for (int ni = 0; ni < 4; ni++) {
                    const uint32_t* bh2 = &fbh[ni >> 1][(ni & 1) * 2];
                    MMA_FP16(acc[mi][ni], fah[mi], bh2[0], bh2[1]);
                    MMA_F16A(accL[mi][ni], fal[mi], bh2[0], bh2[1]);
                    if (passes == 3) {
                        const uint32_t* bl2 = &fbl[ni >> 1][(ni & 1) * 2];
                        MMA_F16A(accL[mi][ni], fah[mi], bl2[0], bl2[1]);
                    }
                }
        }
        __syncthreads();
    }

    int g  = lane >> 2;
    int c2 = (lane & 3) * 2;
#pragma unroll
    for (int mi = 0; mi < 4; mi++)
#pragma unroll
        for (int ni = 0; ni < 4; ni++) {
            add_h2(&acc[mi][ni][0], accL[mi][ni][0]);
            add_h2(&acc[mi][ni][2], accL[mi][ni][1]);
            int row = m0 + wm * 64 + mi * 16 + g;
            int col = n0 + wn * 32 + ni * 8 + c2;
            *(float2*)(C + (size_t)row * N + col)       = make_float2(acc[mi][ni][0], acc[mi][ni][1]);
            *(float2*)(C + (size_t)(row + 8) * N + col) = make_float2(acc[mi][ni][2], acc[mi][ni][3]);
        }
}

// fused QKV projection: one launch, region by blockIdx.x
__global__ __launch_bounds__(256) void gemm_qkv_kernel(
    const __half* __restrict__ Ah, const __half* __restrict__ Al,
    const __half* __restrict__ wqh, const __half* __restrict__ wql,
    const __half* __restrict__ wkh, const __half* __restrict__ wkl,
    const __half* __restrict__ wvh,
    float* __restrict__ gq, float* __restrict__ gk, float* __restrict__ gv)
{
    extern __shared__ __half smbuf[];
    const int bx = blockIdx.x;
    const int m0 = blockIdx.y * 128;
    const __half *Bh, *Bl;
    float* C;
    int N, n0, passes;
    if (bx < 16)      { Bh = wqh; Bl = wql; C = gq; N = QN;  n0 = bx * 128;        passes = 3; }
    else if (bx < 24) { Bh = wkh; Bl = wkl; C = gk; N = KVN; n0 = (bx - 16) * 128; passes = 3; }
    else              { Bh = wvh; Bl = wvh; C = gv; N = KVN; n0 = (bx - 24) * 128; passes = 2; }
    gemm_body(Ah, Al, Bh, Bl, C, N, HID, m0, n0, passes, smbuf);
}

// output projection (2-pass)
__global__ __launch_bounds__(256) void gemm_wo_kernel(
    const __half* __restrict__ Ah, const __half* __restrict__ Al,
    const __half* __restrict__ Bh, float* __restrict__ C)
{
    extern __shared__ __half smbuf[];
    gemm_body(Ah, Al, Bh, Bh, C, HID, QN, blockIdx.y * 128, blockIdx.x * 128, 2, smbuf);
}

// =====================================================================
// Fused RMSNorm (+weight) + RoPE — warp-per-head (R7, unchanged)
// =====================================================================
__global__ __launch_bounds__(256) void norm_rope_kernel(
    const float* __restrict__ q, const float* __restrict__ k, const float* __restrict__ v,
    const float* __restrict__ cosp, const float* __restrict__ sinp,
    const float* __restrict__ qw, const float* __restrict__ kw,
    __half* __restrict__ qh, __half* __restrict__ ql,
    __half* __restrict__ kh, __half* __restrict__ kl,
    __half* __restrict__ vh)
{
    const int lane = threadIdx.x & 31;
    const int row  = blockIdx.x * 8 + (threadIdx.x >> 5);
    const int s    = row >> 4;
    const int idx  = row & 15;

    const float* base;
    const float* w;
    __half *oh, *ol;
    bool rope;
    if (idx < 8) {
        base = q + (size_t)s * QN + idx * DH; w = qw; rope = true;
        oh = qh + (size_t)s * QN + idx * DH; ol = ql + (size_t)s * QN + idx * DH;
    } else if (idx < 12) {
        base = k + (size_t)s * KVN + (idx - 8) * DH; w = kw; rope = true;
        oh = kh + (size_t)s * KVN + (idx - 8) * DH; ol = kl + (size_t)s * KVN + (idx - 8) * DH;
    } else {
        base = v + (size_t)s * KVN + (idx - 12) * DH; w = nullptr; rope = false;
        oh = vh + (size_t)s * KVN + (idx - 12) * DH; ol = nullptr;
    }

    const int d0 = lane * 8;
    float x[8];
    *(float4*)&x[0] = *(const float4*)(base + d0);
    *(float4*)&x[4] = *(const float4*)(base + d0 + 4);

    float ss = 0.f;
#pragma unroll
    for (int j = 0; j < 8; j++) ss += x[j] * x[j];
#pragma unroll
    for (int o = 16; o; o >>= 1) ss += __shfl_xor_sync(0xffffffffu, ss, o);

    float inv = rsqrtf(ss * (1.0f / 256.0f) + 1e-6f);
    float y[8];
#pragma unroll
    for (int j = 0; j < 8; j++) y[j] = x[j] * inv;
    if (w) {
        float wv[8];
        *(float4*)&wv[0] = *(const float4*)(w + d0);
        *(float4*)&wv[4] = *(const float4*)(w + d0 + 4);
#pragma unroll
        for (int j = 0; j < 8; j++) y[j] *= wv[j];
    }

    float out[8];
    if (rope) {
        float c[8], si[8];
        *(float4*)&c[0]  = *(const float4*)(cosp + (size_t)s * DH + d0);
        *(float4*)&c[4]  = *(const float4*)(cosp + (size_t)s * DH + d0 + 4);
        *(float4*)&si[0] = *(const float4*)(sinp + (size_t)s * DH + d0);
        *(float4*)&si[4] = *(const float4*)(sinp + (size_t)s * DH + d0 + 4);
#pragma unroll
        for (int j = 0; j < 8; j++) {
            float pv = __shfl_xor_sync(0xffffffffu, y[j], 16);
            float rh = (lane < 16) ? -pv : pv;
            out[j] = y[j] * c[j] + rh * si[j];
        }
    } else {
#pragma unroll
        for (int j = 0; j < 8; j++) out[j] = y[j];
    }

    __half hi8[8], lo8[8];
#pragma unroll
    for (int j = 0; j < 8; j++) {
        hi8[j] = __float2half_rn(out[j]);
        lo8[j] = __float2half_rn(out[j] - __half2float(hi8[j]));
    }
    *(uint4*)(oh + d0) = *(uint4*)hi8;
    if (ol) *(uint4*)(ol + d0) = *(uint4*)lo8;
}

// =====================================================================
// TC flash attention: XOR-swizzled smem (no padding) + double-buffered
// K/V so loads overlap compute. QK 3-pass, PV 2-pass (R7 precision).
// smem: Qh,Ql 128x512B + 2 stages x (Kh,Kl,Vh 32x512B) = 229376 B
// =====================================================================
#define KVSTAGE  (3 * 32 * 512)                  // 49152 B
#define ATT_SM_BYTES (2 * 128 * 512 + 2 * KVSTAGE)  // 229376 B

__global__ __launch_bounds__(256, 1) void attn_tc_kernel(
    const __half* __restrict__ Qh, const __half* __restrict__ Ql,
    const __half* __restrict__ Kh, const __half* __restrict__ Kl,
    const __half* __restrict__ Vh,
    __half* __restrict__ Oh, __half* __restrict__ Ol)
{
    extern __shared__ __half sm2[];
    const int t    = threadIdx.x;
    const int lane = t & 31;
    const int w    = t >> 5;
    const int q0   = blockIdx.x * 128;
    const int h    = blockIdx.y;
    const int kvh  = h >> 1;

    const uint32_t sQh = smem_u32(sm2);
    const uint32_t sQl = sQh + 128 * 512;
    uint32_t sK_h[2], sK_l[2], sV_h[2];
#pragma unroll
    for (int st = 0; st < 2; st++) {
        uint32_t b = sQh + 2 * 128 * 512 + st * KVSTAGE;
        sK_h[st] = b;
        sK_l[st] = b + 32 * 512;
        sV_h[st] = b + 2 * 32 * 512;
    }

    // ---- Q load (group 0) ----
    const __half* gqh = Qh + (size_t)q0 * QN + h * DH;
    const __half* gql = Ql + (size_t)q0 * QN + h * DH;
#pragma unroll
    for (int it = 0; it < 16; it++) {
        int id = t + it * 256;
        int row = id >> 5, cb = id & 31;
        uint32_t d = swz(row, cb);
        size_t g = (size_t)row * QN + cb * 8;
        CP16(sQh + d, gqh + g);
        CP16(sQl + d, gql + g);
    }
    CP_COMMIT();

    auto issueKV = [&](int k0, int st) {
        const __half* gkh = Kh + (size_t)k0 * KVN + kvh * DH;
        const __half* gkl = Kl + (size_t)k0 * KVN + kvh * DH;
        const __half* gvh = Vh + (size_t)k0 * KVN + kvh * DH;
#pragma unroll
        for (int it = 0; it < 4; it++) {
            int id = t + it * 256;
            int row = id >> 5, cb = id & 31;
            uint32_t d = swz(row, cb);
            size_t g = (size_t)row * KVN + cb * 8;
            CP16(sK_h[st] + d, gkh + g);
            CP16(sK_l[st] + d, gkl + g);
            CP16(sV_h[st] + d, gvh + g);
        }
        CP_COMMIT();
    };

    float o[32][4];
#pragma unroll
    for (int dt = 0; dt < 32; dt++)
#pragma unroll
        for (int r = 0; r < 4; r++) o[dt][r] = 0.f;
    float mrow[2] = {-1e30f, -1e30f};
    float lrow[2] = {0.f, 0.f};

    const int kb_lo = max(0, q0 - (WIN - 1)) >> 5;
    const int kb_hi = (q0 + 127) >> 5;
    const int qw_lo = q0 + w * 16;
    const int gq_row = lane >> 2;
    const int t4 = lane & 3;

    issueKV(kb_lo * 32, 0);   // preload first keyblock (group 1)

    for (int kb = kb_lo; kb <= kb_hi; kb++) {
        const int st = (kb - kb_lo) & 1;
        if (kb < kb_hi) {
            issueKV((kb + 1) * 32, st ^ 1);
            CP_WAIT1();                       // current stage (and Q) complete
        } else {
            CP_WAIT0();
        }
        __syncthreads();

        const int k0 = kb * 32;
        bool active = (k0 <= qw_lo + 15) && (k0 + 31 >= qw_lo - (WIN - 1));
        if (active) {
            const uint32_t kh_s = sK_h[st], kl_s = sK_l[st], vh_s = sV_h[st];

            float s[4][4];
            uint32_t sl[4][2];
#pragma unroll
            for (int tl = 0; tl < 4; tl++) {
#pragma unroll
                for (int r = 0; r < 4; r++) s[tl][r] = 0.f;
                sl[tl][0] = 0u; sl[tl][1] = 0u;
            }

#pragma unroll
            for (int dc = 0; dc < 16; dc++) {
                uint32_t qa[4], qb[4], k1h[4], k2h[4], k1l[4], k2l[4];
                int cb = dc * 2 + (lane >> 4);
                uint32_t qoff = swz(w * 16 + (lane & 15), cb);
                LDSM4(qa, sQh + qoff);
                LDSM4(qb, sQl + qoff);
                uint32_t koff = swz(lane & 15, cb);      // rows 0-15
                LDSM4(k1h, kh_s + koff);
                LDSM4(k2h, kh_s + koff + 16 * 512);      // rows 16-31: same xor (row&7 preserved)
                LDSM4(k1l, kl_s + koff);
                LDSM4(k2l, kl_s + koff + 16 * 512);

                MMA_FP16(s[0], qa, k1h[0], k1h[2]);
                MMA_FP16(s[1], qa, k1h[1], k1h[3]);
                MMA_FP16(s[2], qa, k2h[0], k2h[2]);
                MMA_FP16(s[3], qa, k2h[1], k2h[3]);
                MMA_F16A(sl[0], qa, k1l[0], k1l[2]);
                MMA_F16A(sl[1], qa, k1l[1], k1l[3]);
                MMA_F16A(sl[2], qa, k2l[0], k2l[2]);
                MMA_F16A(sl[3], qa, k2l[1], k2l[3]);
                MMA_F16A(sl[0], qb, k1h[0], k1h[2]);
                MMA_F16A(sl[1], qb, k1h[1], k1h[3]);
                MMA_F16A(sl[2], qb, k2h[0], k2h[2]);
                MMA_F16A(sl[3], qb, k2h[1], k2h[3]);
            }
#pragma unroll
            for (int tl = 0; tl < 4; tl++) {
                add_h2(&s[tl][0], sl[tl][0]);
                add_h2(&s[tl][2], sl[tl][1]);
            }

            float corr[2];
#pragma unroll
            for (int r = 0; r < 2; r++) {
                int qg = qw_lo + gq_row + r * 8;
                float mx = -1e30f;
#pragma unroll
                for (int tl = 0; tl < 4; tl++) {
#pragma unroll
                    for (int c = 0; c < 2; c++) {
                        int kg = k0 + tl * 8 + 2 * t4 + c;
                        bool ok = (kg <= qg) && (qg - kg < WIN);
                        if (!ok) s[tl][r * 2 + c] = -1e30f;
                        mx = fmaxf(mx, s[tl][r * 2 + c]);
                    }
                }
                mx = fmaxf(mx, __shfl_xor_sync(0xffffffffu, mx, 1));
                mx = fmaxf(mx, __shfl_xor_sync(0xffffffffu, mx, 2));
                float m_new = fmaxf(mrow[r], mx);
                float mexp = (m_new <= -1e29f) ? 0.f : m_new;
                float sum = 0.f;
#pragma unroll
                for (int tl = 0; tl < 4; tl++) {
#pragma unroll
                    for (int c = 0; c < 2; c++) {
                        float p = __expf(s[tl][r * 2 + c] - mexp);
                        s[tl][r * 2 + c] = p;
                        sum += p;
                    }
                }
                sum += __shfl_xor_sync(0xffffffffu, sum, 1);
                sum += __shfl_xor_sync(0xffffffffu, sum, 2);
                corr[r] = __expf(mrow[r] - m_new);
                mrow[r] = m_new;
                lrow[r] = lrow[r] * corr[r] + sum;
            }

            uint32_t ph[2][4], pl[2][4];
#pragma unroll
            for (int kc = 0; kc < 2; kc++) {
#pragma unroll
                for (int r2 = 0; r2 < 4; r2++) {
                    int tl = kc * 2 + (r2 >> 1);
                    int r  = r2 & 1;
                    float p0 = s[tl][r * 2 + 0];
                    float p1 = s[tl][r * 2 + 1];
                    __half h0 = __float2half_rn(p0);
                    __half h1 = __float2half_rn(p1);
                    __half2 hh = __halves2half2(h0, h1);
                    __half2 ll = __halves2half2(__float2half_rn(p0 - __half2float(h0)),
                                                __float2half_rn(p1 - __half2float(h1)));
                    ph[kc][r2] = *(uint32_t*)&hh;
                    pl[kc][r2] = *(uint32_t*)&ll;
                }
            }

#pragma unroll
            for (int dt = 0; dt < 32; dt++) {
                o[dt][0] *= corr[0]; o[dt][1] *= corr[0];
                o[dt][2] *= corr[1]; o[dt][3] *= corr[1];
            }

#pragma unroll
            for (int dg = 0; dg < 16; dg++) {
#pragma unroll
                for (int kc = 0; kc < 2; kc++) {
                    uint32_t vh4[4];
                    int row_v = kc * 16 + (lane & 7) + ((lane >> 3) & 1) * 8;
                    int cb_v  = dg * 2 + ((lane >> 4) & 1);
                    LDSM4T(vh4, vh_s + swz(row_v, cb_v));
                    MMA_FP16(o[2 * dg],     ph[kc], vh4[0], vh4[1]);
                    MMA_FP16(o[2 * dg + 1], ph[kc], vh4[2], vh4[3]);
                    MMA_FP16(o[2 * dg],     pl[kc], vh4[0], vh4[1]);
                    MMA_FP16(o[2 * dg + 1], pl[kc], vh4[2], vh4[3]);
                }
            }
        }
        __syncthreads();   // protect stage st^1 (next iteration's cp target)
    }

    // finalize -> fp16 hi/lo output (A operand of wo GEMM)
    float inv0 = 1.f / lrow[0];
    float inv1 = 1.f / lrow[1];
    size_t r0 = (size_t)(q0 + w * 16 + gq_row) * QN + h * DH;
    size_t r1 = r0 + (size_t)8 * QN;
#pragma unroll
    for (int dt = 0; dt < 32; dt++) {
        int col = dt * 8 + 2 * t4;
        float a0 = o[dt][0] * inv0, a1 = o[dt][1] * inv0;
        float b0 = o[dt][2] * inv1, b1 = o[dt][3] * inv1;
        __half ha0 = __float2half_rn(a0), ha1 = __float2half_rn(a1);
        __half hb0 = __float2half_rn(b0), hb1 = __float2half_rn(b1);
        *(__half2*)(Oh + r0 + col) = __halves2half2(ha0, ha1);
        *(__half2*)(Oh + r1 + col) = __halves2half2(hb0, hb1);
        *(__half2*)(Ol + r0 + col) = __halves2half2(
            __float2half_rn(a0 - __half2float(ha0)), __float2half_rn(a1 - __half2float(ha1)));
        *(__half2*)(Ol + r1 + col) = __halves2half2(
            __float2half_rn(b0 - __half2float(hb0)), __float2half_rn(b1 - __half2float(hb1)));
    }
}

// =====================================================================
// kernel_launch
// =====================================================================
extern "C" void kernel_launch(void* const* d_in, const int* in_sizes, int n_in,
                              void* d_out, int out_size)
{
    const float* hs   = (const float*)d_in[0];
    const float* cosp = (const float*)d_in[1];
    const float* sinp = (const float*)d_in[2];
    const float* wq   = (const float*)d_in[3];
    const float* wk   = (const float*)d_in[4];
    const float* wv   = (const float*)d_in[5];
    const float* wo   = (const float*)d_in[6];
    const float* qw   = (const float*)d_in[7];
    const float* kw   = (const float*)d_in[8];
    float* out = (float*)d_out;

    float *gq, *gk, *gv;
    cudaGetSymbolAddress((void**)&gq, g_q);
    cudaGetSymbolAddress((void**)&gk, g_k);
    cudaGetSymbolAddress((void**)&gv, g_v);

    __half *hsh, *hsl, *wqh, *wql, *wkh, *wkl, *wvh, *woh, *ath, *atl;
    __half *qh, *ql, *kh, *kl, *vh;
    cudaGetSymbolAddress((void**)&hsh, g_hs_h); cudaGetSymbolAddress((void**)&hsl, g_hs_l);
    cudaGetSymbolAddress((void**)&wqh, g_wq_h); cudaGetSymbolAddress((void**)&wql, g_wq_l);
    cudaGetSymbolAddress((void**)&wkh, g_wk_h); cudaGetSymbolAddress((void**)&wkl, g_wk_l);
    cudaGetSymbolAddress((void**)&wvh, g_wv_h);
    cudaGetSymbolAddress((void**)&woh, g_wo_h);
    cudaGetSymbolAddress((void**)&ath, g_at_h); cudaGetSymbolAddress((void**)&atl, g_at_l);
    cudaGetSymbolAddress((void**)&qh, g_qh);    cudaGetSymbolAddress((void**)&ql, g_ql);
    cudaGetSymbolAddress((void**)&kh, g_kh);    cudaGetSymbolAddress((void**)&kl, g_kl);
    cudaGetSymbolAddress((void**)&vh, g_vh);

    cudaFuncSetAttribute(gemm_qkv_kernel, cudaFuncAttributeMaxDynamicSharedMemorySize,
                         GEMM_SMEM_BYTES);
    cudaFuncSetAttribute(gemm_wo_kernel, cudaFuncAttributeMaxDynamicSharedMemorySize,
                         GEMM_SMEM_BYTES);
    cudaFuncSetAttribute(attn_tc_kernel, cudaFuncAttributeMaxDynamicSharedMemorySize,
                         ATT_SM_BYTES);

    // all splits in one launch
    split_all_kernel<<<20480, 256>>>(hs, wq, wk, wv, wo,
                                     hsh, hsl, wqh, wql, wkh, wkl, wvh, woh);

    // fused QKV projections (q,k 3-pass; v 2-pass)
    gemm_qkv_kernel<<<dim3(32, S / 128), 256, GEMM_SMEM_BYTES>>>(
        hsh, hsl, wqh, wql, wkh, wkl, wvh, gq, gk, gv);

    // RMSNorm + RoPE
    norm_rope_kernel<<<S * 16 / 8, 256>>>(gq, gk, gv, cosp, sinp, qw, kw,
                                          qh, ql, kh, kl, vh);

    // attention (double-buffered K/V)
    attn_tc_kernel<<<dim3(S / 128, NH), 256, ATT_SM_BYTES>>>(
        qh, ql, kh, kl, vh, ath, atl);

    // output projection (2-pass)
    gemm_wo_kernel<<<dim3(HID / 128, S / 128), 256, GEMM_SMEM_BYTES>>>(
        ath, atl, woh, out);
}

// round 10
// speedup vs baseline: 3.3538x; 1.0291x over previous
#include <cuda_runtime.h>
#include <cuda_fp16.h>
#include <math.h>
#include <stdint.h>

// ---------------- problem constants ----------------
#define S     2048
#define HID   2560
#define NH    8
#define NKV   4
#define DH    256
#define WIN   1024
#define QN    (NH*DH)    // 2048
#define KVN   (NKV*DH)   // 1024

// ---------------- scratch ----------------
__device__ float g_q[S * QN];
__device__ float g_k[S * KVN];
__device__ float g_v[S * KVN];

__device__ __half g_hs_h[S * HID],  g_hs_l[S * HID];
__device__ __half g_wq_h[HID * QN], g_wq_l[HID * QN];
__device__ __half g_wk_h[HID * KVN], g_wk_l[HID * KVN];
__device__ __half g_wv_h[HID * KVN];
__device__ __half g_wo_h[QN * HID];
__device__ __half g_at_h[S * QN],   g_at_l[S * QN];

__device__ __half g_qh[S * QN],  g_ql[S * QN];
__device__ __half g_kh[S * KVN], g_kl[S * KVN];
__device__ __half g_vh[S * KVN];

// ---------------- PTX helpers ----------------
#define CP16(dst_u32, src_ptr) \
    asm volatile("cp.async.cg.shared.global [%0], [%1], 16;\n" :: "r"(dst_u32), "l"(src_ptr))
#define CP_COMMIT()  asm volatile("cp.async.commit_group;\n")
#define CP_WAIT0()   asm volatile("cp.async.wait_group 0;\n" ::: "memory")

#define LDSM4(R, addr) \
    asm volatile("ldmatrix.sync.aligned.m8n8.x4.shared.b16 {%0,%1,%2,%3}, [%4];\n" \
        : "=r"((R)[0]), "=r"((R)[1]), "=r"((R)[2]), "=r"((R)[3]) : "r"(addr))
#define LDSM4T(R, addr) \
    asm volatile("ldmatrix.sync.aligned.m8n8.x4.trans.shared.b16 {%0,%1,%2,%3}, [%4];\n" \
        : "=r"((R)[0]), "=r"((R)[1]), "=r"((R)[2]), "=r"((R)[3]) : "r"(addr))

#define MMA_FP16(d, a, b0, b1) \
    asm volatile("mma.sync.aligned.m16n8k16.row.col.f32.f16.f16.f32 " \
        "{%0,%1,%2,%3},{%4,%5,%6,%7},{%8,%9},{%0,%1,%2,%3};\n" \
        : "+f"((d)[0]), "+f"((d)[1]), "+f"((d)[2]), "+f"((d)[3]) \
        : "r"((a)[0]), "r"((a)[1]), "r"((a)[2]), "r"((a)[3]), "r"(b0), "r"(b1))

#define MMA_F16A(d, a, b0, b1) \
    asm volatile("mma.sync.aligned.m16n8k16.row.col.f16.f16.f16.f16 " \
        "{%0,%1},{%2,%3,%4,%5},{%6,%7},{%0,%1};\n" \
        : "+r"((d)[0]), "+r"((d)[1]) \
        : "r"((a)[0]), "r"((a)[1]), "r"((a)[2]), "r"((a)[3]), "r"(b0), "r"(b1))

__device__ __forceinline__ uint32_t smem_u32(const void* p) {
    return (uint32_t)__cvta_generic_to_shared(p);
}
__device__ __forceinline__ void add_h2(float* f01, uint32_t packed) {
    __half2 h = *(__half2*)&packed;
    float2 v = __half22float2(h);
    f01[0] += v.x; f01[1] += v.y;
}
// XOR swizzle for 512B rows
__device__ __forceinline__ uint32_t swz(int row, int cb) {
    return (uint32_t)(row * 512 + ((cb ^ (row & 7)) << 4));
}

// =====================================================================
// Fused split kernel (one launch)
// =====================================================================
__global__ __launch_bounds__(256) void split_all_kernel(
    const float* __restrict__ hs, const float* __restrict__ wq,
    const float* __restrict__ wk, const float* __restrict__ wv,
    const float* __restrict__ wo,
    __half* __restrict__ hsh, __half* __restrict__ hsl,
    __half* __restrict__ wqh, __half* __restrict__ wql,
    __half* __restrict__ wkh, __half* __restrict__ wkl,
    __half* __restrict__ wvh, __half* __restrict__ woh)
{
    int b = blockIdx.x;
    const float* x; __half *h, *l;
    if (b < 5120)       { x = hs; h = hsh; l = hsl; }
    else if (b < 10240) { x = wq; h = wqh; l = wql; b -= 5120; }
    else if (b < 12800) { x = wk; h = wkh; l = wkl; b -= 10240; }
    else if (b < 15360) { x = wv; h = wvh; l = nullptr; b -= 12800; }
    else                { x = wo; h = woh; l = nullptr; b -= 15360; }

    int i = (b * 256 + threadIdx.x) * 4;
    float4 v = *(const float4*)(x + i);
    __half h0 = __float2half_rn(v.x), h1 = __float2half_rn(v.y);
    __half h2 = __float2half_rn(v.z), h3 = __float2half_rn(v.w);
    *(__half2*)(h + i)     = __halves2half2(h0, h1);
    *(__half2*)(h + i + 2) = __halves2half2(h2, h3);
    if (l) {
        *(__half2*)(l + i)     = __halves2half2(
            __float2half_rn(v.x - __half2float(h0)), __float2half_rn(v.y - __half2float(h1)));
        *(__half2*)(l + i + 2) = __halves2half2(
            __float2half_rn(v.z - __half2float(h2)), __float2half_rn(v.w - __half2float(h3)));
    }
}

// =====================================================================
// fp16 TC GEMM body — PASSES is a compile-time template parameter.
// hi pass f32-acc + cross passes f16-acc. 128x128x32 tile, 8 warps.
// =====================================================================
#define AS_STR 40
#define BS_STR 136
#define ABUF   (128 * AS_STR)
#define BBUF   (32 * BS_STR)
#define BUFELEM (2 * ABUF + 2 * BBUF)
#define GEMM_SMEM_BYTES (2 * BUFELEM * 2)

template <int PASSES>
__device__ __forceinline__ void gemm_body(
    const __half* __restrict__ Ah, const __half* __restrict__ Al,
    const __half* __restrict__ Bh, const __half* __restrict__ Bl,
    float* __restrict__ C, int N, int K, int m0, int n0,
    __half* smbuf)
{
    const int t    = threadIdx.x;
    const int lane = t & 31;
    const int wid  = t >> 5;
    const int wm   = wid >> 2;
    const int wn   = wid & 3;

    float acc[4][4][4];
    uint32_t accL[4][4][2];
#pragma unroll
    for (int mi = 0; mi < 4; mi++)
#pragma unroll
        for (int ni = 0; ni < 4; ni++) {
#pragma unroll
            for (int r = 0; r < 4; r++) acc[mi][ni][r] = 0.f;
            accL[mi][ni][0] = 0u; accL[mi][ni][1] = 0u;
        }

    uint32_t sbase[2][4];
#pragma unroll
    for (int b = 0; b < 2; b++) {
        __half* p = smbuf + b * BUFELEM;
        sbase[b][0] = smem_u32(p);
        sbase[b][1] = smem_u32(p + ABUF);
        sbase[b][2] = smem_u32(p + 2 * ABUF);
        sbase[b][3] = smem_u32(p + 2 * ABUF + BBUF);
    }

    auto issue = [&](int k0, int buf) {
#pragma unroll
        for (int p = 0; p < 2; p++) {
            int id = t + p * 256;
            int am = id >> 2, ac = (id & 3) * 8;
            size_t aoff = (size_t)(m0 + am) * K + k0 + ac;
            uint32_t ad = (uint32_t)(am * AS_STR + ac) * 2;
            CP16(sbase[buf][0] + ad, Ah + aoff);
            CP16(sbase[buf][1] + ad, Al + aoff);
            int bk = id >> 4, bc = (id & 15) * 8;
            size_t boff = (size_t)(k0 + bk) * N + n0 + bc;
            uint32_t bd = (uint32_t)(bk * BS_STR + bc) * 2;
            CP16(sbase[buf][2] + bd, Bh + boff);
            if (PASSES == 3) CP16(sbase[buf][3] + bd, Bl + boff);
        }
        CP_COMMIT();
    };

    issue(0, 0);
    const int nIter = K / 32;

    for (int it = 0; it < nIter; it++) {
        CP_WAIT0();
        __syncthreads();
        if (it + 1 < nIter) issue((it + 1) * 32, (it + 1) & 1);

        const int buf = it & 1;
        const uint32_t ah_s = sbase[buf][0];
        const uint32_t al_s = sbase[buf][1];
        const uint32_t bh_s = sbase[buf][2];
        const uint32_t bl_s = sbase[buf][3];

#pragma unroll
        for (int ks = 0; ks < 32; ks += 16) {
            uint32_t fah[4][4], fal[4][4], fbh[2][4], fbl[2][4];

            int arow = lane & 15;
            int acol = ks + ((lane >> 4) & 1) * 8;
#pragma unroll
            for (int mi = 0; mi < 4; mi++) {
                uint32_t off = (uint32_t)((wm * 64 + mi * 16 + arow) * AS_STR + acol) * 2;
                LDSM4(fah[mi], ah_s + off);
                LDSM4(fal[mi], al_s + off);
            }

            int bkrow = ks + (lane & 7) + ((lane >> 3) & 1) * 8;
#pragma unroll
            for (int np = 0; np < 2; np++) {
                int bcol = wn * 32 + np * 16 + ((lane >> 4) & 1) * 8;
                uint32_t off = (uint32_t)(bkrow * BS_STR + bcol) * 2;
                LDSM4T(fbh[np], bh_s + off);
                if (PASSES == 3) LDSM4T(fbl[np], bl_s + off);
            }

#pragma unroll
            for (int mi = 0; mi < 4; mi++)
#pragma unroll
                for (int ni = 0; ni < 4; ni++) {
                    const uint32_t* bh2 = &fbh[ni >> 1][(ni & 1) * 2];
                    MMA_FP16(acc[mi][ni], fah[mi], bh2[0], bh2[1]);
                    MMA_F16A(accL[mi][ni], fal[mi], bh2[0], bh2[1]);
                    if (PASSES == 3) {
                        const uint32_t* bl2 = &fbl[ni >> 1][(ni & 1) * 2];
                        MMA_F16A(accL[mi][ni], fah[mi], bl2[0], bl2[1]);
                    }
                }
        }
        __syncthreads();
    }

    int g  = lane >> 2;
    int c2 = (lane & 3) * 2;
#pragma unroll
    for (int mi = 0; mi < 4; mi++)
#pragma unroll
        for (int ni = 0; ni < 4; ni++) {
            add_h2(&acc[mi][ni][0], accL[mi][ni][0]);
            add_h2(&acc[mi][ni][2], accL[mi][ni][1]);
            int row = m0 + wm * 64 + mi * 16 + g;
            int col = n0 + wn * 32 + ni * 8 + c2;
            *(float2*)(C + (size_t)row * N + col)       = make_float2(acc[mi][ni][0], acc[mi][ni][1]);
            *(float2*)(C + (size_t)(row + 8) * N + col) = make_float2(acc[mi][ni][2], acc[mi][ni][3]);
        }
}

// fused QKV projection — compile-time pass dispatch per region
__global__ __launch_bounds__(256) void gemm_qkv_kernel(
    const __half* __restrict__ Ah, const __half* __restrict__ Al,
    const __half* __restrict__ wqh, const __half* __restrict__ wql,
    const __half* __restrict__ wkh, const __half* __restrict__ wkl,
    const __half* __restrict__ wvh,
    float* __restrict__ gq, float* __restrict__ gk, float* __restrict__ gv)
{
    extern __shared__ __half smbuf[];
    const int bx = blockIdx.x;
    const int m0 = blockIdx.y * 128;
    if (bx < 16)
        gemm_body<3>(Ah, Al, wqh, wql, gq, QN, HID, m0, bx * 128, smbuf);
    else if (bx < 24)
        gemm_body<3>(Ah, Al, wkh, wkl, gk, KVN, HID, m0, (bx - 16) * 128, smbuf);
    else
        gemm_body<2>(Ah, Al, wvh, wvh, gv, KVN, HID, m0, (bx - 24) * 128, smbuf);
}

// output projection (2-pass, compile-time)
__global__ __launch_bounds__(256) void gemm_wo_kernel(
    const __half* __restrict__ Ah, const __half* __restrict__ Al,
    const __half* __restrict__ Bh, float* __restrict__ C)
{
    extern __shared__ __half smbuf[];
    gemm_body<2>(Ah, Al, Bh, Bh, C, HID, QN, blockIdx.y * 128, blockIdx.x * 128, smbuf);
}

// =====================================================================
// Fused RMSNorm (+weight) + RoPE — warp-per-head (unchanged)
// =====================================================================
__global__ __launch_bounds__(256) void norm_rope_kernel(
    const float* __restrict__ q, const float* __restrict__ k, const float* __restrict__ v,
    const float* __restrict__ cosp, const float* __restrict__ sinp,
    const float* __restrict__ qw, const float* __restrict__ kw,
    __half* __restrict__ qh, __half* __restrict__ ql,
    __half* __restrict__ kh, __half* __restrict__ kl,
    __half* __restrict__ vh)
{
    const int lane = threadIdx.x & 31;
    const int row  = blockIdx.x * 8 + (threadIdx.x >> 5);
    const int s    = row >> 4;
    const int idx  = row & 15;

    const float* base;
    const float* w;
    __half *oh, *ol;
    bool rope;
    if (idx < 8) {
        base = q + (size_t)s * QN + idx * DH; w = qw; rope = true;
        oh = qh + (size_t)s * QN + idx * DH; ol = ql + (size_t)s * QN + idx * DH;
    } else if (idx < 12) {
        base = k + (size_t)s * KVN + (idx - 8) * DH; w = kw; rope = true;
        oh = kh + (size_t)s * KVN + (idx - 8) * DH; ol = kl + (size_t)s * KVN + (idx - 8) * DH;
    } else {
        base = v + (size_t)s * KVN + (idx - 12) * DH; w = nullptr; rope = false;
        oh = vh + (size_t)s * KVN + (idx - 12) * DH; ol = nullptr;
    }

    const int d0 = lane * 8;
    float x[8];
    *(float4*)&x[0] = *(const float4*)(base + d0);
    *(float4*)&x[4] = *(const float4*)(base + d0 + 4);

    float ss = 0.f;
#pragma unroll
    for (int j = 0; j < 8; j++) ss += x[j] * x[j];
#pragma unroll
    for (int o = 16; o; o >>= 1) ss += __shfl_xor_sync(0xffffffffu, ss, o);

    float inv = rsqrtf(ss * (1.0f / 256.0f) + 1e-6f);
    float y[8];
#pragma unroll
    for (int j = 0; j < 8; j++) y[j] = x[j] * inv;
    if (w) {
        float wv[8];
        *(float4*)&wv[0] = *(const float4*)(w + d0);
        *(float4*)&wv[4] = *(const float4*)(w + d0 + 4);
#pragma unroll
        for (int j = 0; j < 8; j++) y[j] *= wv[j];
    }

    float out[8];
    if (rope) {
        float c[8], si[8];
        *(float4*)&c[0]  = *(const float4*)(cosp + (size_t)s * DH + d0);
        *(float4*)&c[4]  = *(const float4*)(cosp + (size_t)s * DH + d0 + 4);
        *(float4*)&si[0] = *(const float4*)(sinp + (size_t)s * DH + d0);
        *(float4*)&si[4] = *(const float4*)(sinp + (size_t)s * DH + d0 + 4);
#pragma unroll
        for (int j = 0; j < 8; j++) {
            float pv = __shfl_xor_sync(0xffffffffu, y[j], 16);
            float rh = (lane < 16) ? -pv : pv;
            out[j] = y[j] * c[j] + rh * si[j];
        }
    } else {
#pragma unroll
        for (int j = 0; j < 8; j++) out[j] = y[j];
    }

    __half hi8[8], lo8[8];
#pragma unroll
    for (int j = 0; j < 8; j++) {
        hi8[j] = __float2half_rn(out[j]);
        lo8[j] = __float2half_rn(out[j] - __half2float(hi8[j]));
    }
    *(uint4*)(oh + d0) = *(uint4*)hi8;
    if (ol) *(uint4*)(ol + d0) = *(uint4*)lo8;
}

// =====================================================================
// TC flash attention: 64-query tiles, 128 threads (4 warps), 2 CTAs/SM.
// Single KV buffer per CTA; cross-CTA overlap hides load latency.
// smem per CTA: Qh,Ql 64x512B + Kh,Kl,Vh 32x512B = 114688 B
// =====================================================================
#define ATT_SM_BYTES (2 * 64 * 512 + 3 * 32 * 512)   // 114688

__global__ __launch_bounds__(128, 2) void attn_tc_kernel(
    const __half* __restrict__ Qh, const __half* __restrict__ Ql,
    const __half* __restrict__ Kh, const __half* __restrict__ Kl,
    const __half* __restrict__ Vh,
    __half* __restrict__ Oh, __half* __restrict__ Ol)
{
    extern __shared__ __half sm2[];
    const int t    = threadIdx.x;
    const int lane = t & 31;
    const int w    = t >> 5;            // 0..3, warp owns q rows [16w,16w+15]
    const int q0   = blockIdx.x * 64;
    const int h    = blockIdx.y;
    const int kvh  = h >> 1;

    const uint32_t sQh = smem_u32(sm2);
    const uint32_t sQl = sQh + 64 * 512;
    const uint32_t sKh = sQl + 64 * 512;
    const uint32_t sKl = sKh + 32 * 512;
    const uint32_t sVh = sKl + 32 * 512;

    // ---- Q load ----
    const __half* gqh = Qh + (size_t)q0 * QN + h * DH;
    const __half* gql = Ql + (size_t)q0 * QN + h * DH;
#pragma unroll
    for (int it = 0; it < 16; it++) {
        int id = t + it * 128;
        int row = id >> 5, cb = id & 31;
        uint32_t d = swz(row, cb);
        size_t g = (size_t)row * QN + cb * 8;
        CP16(sQh + d, gqh + g);
        CP16(sQl + d, gql + g);
    }
    CP_COMMIT();

    auto issueKV = [&](int k0) {
        const __half* gkh = Kh + (size_t)k0 * KVN + kvh * DH;
        const __half* gkl = Kl + (size_t)k0 * KVN + kvh * DH;
        const __half* gvh = Vh + (size_t)k0 * KVN + kvh * DH;
#pragma unroll
        for (int it = 0; it < 8; it++) {
            int id = t + it * 128;
            int row = id >> 5, cb = id & 31;
            uint32_t d = swz(row, cb);
            size_t g = (size_t)row * KVN + cb * 8;
            CP16(sKh + d, gkh + g);
            CP16(sKl + d, gkl + g);
            CP16(sVh + d, gvh + g);
        }
        CP_COMMIT();
    };

    float o[32][4];
#pragma unroll
    for (int dt = 0; dt < 32; dt++)
#pragma unroll
        for (int r = 0; r < 4; r++) o[dt][r] = 0.f;
    float mrow[2] = {-1e30f, -1e30f};
    float lrow[2] = {0.f, 0.f};

    const int kb_lo = max(0, q0 - (WIN - 1)) >> 5;
    const int kb_hi = (q0 + 63) >> 5;
    const int qw_lo = q0 + w * 16;
    const int gq_row = lane >> 2;
    const int t4 = lane & 3;

    issueKV(kb_lo * 32);

    for (int kb = kb_lo; kb <= kb_hi; kb++) {
        CP_WAIT0();
        __syncthreads();

        const int k0 = kb * 32;
        bool active = (k0 <= qw_lo + 15) && (k0 + 31 >= qw_lo - (WIN - 1));
        if (active) {
            float s[4][4];
            uint32_t sl[4][2];
#pragma unroll
            for (int tl = 0; tl < 4; tl++) {
#pragma unroll
                for (int r = 0; r < 4; r++) s[tl][r] = 0.f;
                sl[tl][0] = 0u; sl[tl][1] = 0u;
            }

#pragma unroll
            for (int dc = 0; dc < 16; dc++) {
                uint32_t qa[4], qb[4], k1h[4], k2h[4], k1l[4], k2l[4];
                int cb = dc * 2 + (lane >> 4);
                uint32_t qoff = swz(w * 16 + (lane & 15), cb);
                LDSM4(qa, sQh + qoff);
                LDSM4(qb, sQl + qoff);
                uint32_t koff = swz(lane & 15, cb);
                LDSM4(k1h, sKh + koff);
                LDSM4(k2h, sKh + koff + 16 * 512);
                LDSM4(k1l, sKl + koff);
                LDSM4(k2l, sKl + koff + 16 * 512);

                MMA_FP16(s[0], qa, k1h[0], k1h[2]);
                MMA_FP16(s[1], qa, k1h[1], k1h[3]);
                MMA_FP16(s[2], qa, k2h[0], k2h[2]);
                MMA_FP16(s[3], qa, k2h[1], k2h[3]);
                MMA_F16A(sl[0], qa, k1l[0], k1l[2]);
                MMA_F16A(sl[1], qa, k1l[1], k1l[3]);
                MMA_F16A(sl[2], qa, k2l[0], k2l[2]);
                MMA_F16A(sl[3], qa, k2l[1], k2l[3]);
                MMA_F16A(sl[0], qb, k1h[0], k1h[2]);
                MMA_F16A(sl[1], qb, k1h[1], k1h[3]);
                MMA_F16A(sl[2], qb, k2h[0], k2h[2]);
                MMA_F16A(sl[3], qb, k2h[1], k2h[3]);
            }
#pragma unroll
            for (int tl = 0; tl < 4; tl++) {
                add_h2(&s[tl][0], sl[tl][0]);
                add_h2(&s[tl][2], sl[tl][1]);
            }

            float corr[2];
#pragma unroll
            for (int r = 0; r < 2; r++) {
                int qg = qw_lo + gq_row + r * 8;
                float mx = -1e30f;
#pragma unroll
                for (int tl = 0; tl < 4; tl++) {
#pragma unroll
                    for (int c = 0; c < 2; c++) {
                        int kg = k0 + tl * 8 + 2 * t4 + c;
                        bool ok = (kg <= qg) && (qg - kg < WIN);
                        if (!ok) s[tl][r * 2 + c] = -1e30f;
                        mx = fmaxf(mx, s[tl][r * 2 + c]);
                    }
                }
                mx = fmaxf(mx, __shfl_xor_sync(0xffffffffu, mx, 1));
                mx = fmaxf(mx, __shfl_xor_sync(0xffffffffu, mx, 2));
                float m_new = fmaxf(mrow[r], mx);
                float mexp = (m_new <= -1e29f) ? 0.f : m_new;
                float sum = 0.f;
#pragma unroll
                for (int tl = 0; tl < 4; tl++) {
#pragma unroll
                    for (int c = 0; c < 2; c++) {
                        float p = __expf(s[tl][r * 2 + c] - mexp);
                        s[tl][r * 2 + c] = p;
                        sum += p;
                    }
                }
                sum += __shfl_xor_sync(0xffffffffu, sum, 1);
                sum += __shfl_xor_sync(0xffffffffu, sum, 2);
                corr[r] = __expf(mrow[r] - m_new);
                mrow[r] = m_new;
                lrow[r] = lrow[r] * corr[r] + sum;
            }

            uint32_t ph[2][4], pl[2][4];
#pragma unroll
            for (int kc = 0; kc < 2; kc++) {
#pragma unroll
                for (int r2 = 0; r2 < 4; r2++) {
                    int tl = kc * 2 + (r2 >> 1);
                    int r  = r2 & 1;
                    float p0 = s[tl][r * 2 + 0];
                    float p1 = s[tl][r * 2 + 1];
                    __half h0 = __float2half_rn(p0);
                    __half h1 = __float2half_rn(p1);
                    __half2 hh = __halves2half2(h0, h1);
                    __half2 ll = __halves2half2(__float2half_rn(p0 - __half2float(h0)),
                                                __float2half_rn(p1 - __half2float(h1)));
                    ph[kc][r2] = *(uint32_t*)&hh;
                    pl[kc][r2] = *(uint32_t*)&ll;
                }
            }

#pragma unroll
            for (int dt = 0; dt < 32; dt++) {
                o[dt][0] *= corr[0]; o[dt][1] *= corr[0];
                o[dt][2] *= corr[1]; o[dt][3] *= corr[1];
            }

#pragma unroll
            for (int dg = 0; dg < 16; dg++) {
#pragma unroll
                for (int kc = 0; kc < 2; kc++) {
                    uint32_t vh4[4];
                    int row_v = kc * 16 + (lane & 7) + ((lane >> 3) & 1) * 8;
                    int cb_v  = dg * 2 + ((lane >> 4) & 1);
                    LDSM4T(vh4, sVh + swz(row_v, cb_v));
                    MMA_FP16(o[2 * dg],     ph[kc], vh4[0], vh4[1]);
                    MMA_FP16(o[2 * dg + 1], ph[kc], vh4[2], vh4[3]);
                    MMA_FP16(o[2 * dg],     pl[kc], vh4[0], vh4[1]);
                    MMA_FP16(o[2 * dg + 1], pl[kc], vh4[2], vh4[3]);
                }
            }
        }
        __syncthreads();
        if (kb < kb_hi) issueKV((kb + 1) * 32);
    }

    // finalize -> fp16 hi/lo output (A operand of wo GEMM)
    float inv0 = 1.f / lrow[0];
    float inv1 = 1.f / lrow[1];
    size_t r0 = (size_t)(q0 + w * 16 + gq_row) * QN + h * DH;
    size_t r1 = r0 + (size_t)8 * QN;
#pragma unroll
    for (int dt = 0; dt < 32; dt++) {
        int col = dt * 8 + 2 * t4;
        float a0 = o[dt][0] * inv0, a1 = o[dt][1] * inv0;
        float b0 = o[dt][2] * inv1, b1 = o[dt][3] * inv1;
        __half ha0 = __float2half_rn(a0), ha1 = __float2half_rn(a1);
        __half hb0 = __float2half_rn(b0), hb1 = __float2half_rn(b1);
        *(__half2*)(Oh + r0 + col) = __halves2half2(ha0, ha1);
        *(__half2*)(Oh + r1 + col) = __halves2half2(hb0, hb1);
        *(__half2*)(Ol + r0 + col) = __halves2half2(
            __float2half_rn(a0 - __half2float(ha0)), __float2half_rn(a1 - __half2float(ha1)));
        *(__half2*)(Ol + r1 + col) = __halves2half2(
            __float2half_rn(b0 - __half2float(hb0)), __float2half_rn(b1 - __half2float(hb1)));
    }
}

// =====================================================================
// kernel_launch
// =====================================================================
extern "C" void kernel_launch(void* const* d_in, const int* in_sizes, int n_in,
                              void* d_out, int out_size)
{
    const float* hs   = (const float*)d_in[0];
    const float* cosp = (const float*)d_in[1];
    const float* sinp = (const float*)d_in[2];
    const float* wq   = (const float*)d_in[3];
    const float* wk   = (const float*)d_in[4];
    const float* wv   = (const float*)d_in[5];
    const float* wo   = (const float*)d_in[6];
    const float* qw   = (const float*)d_in[7];
    const float* kw   = (const float*)d_in[8];
    float* out = (float*)d_out;

    float *gq, *gk, *gv;
    cudaGetSymbolAddress((void**)&gq, g_q);
    cudaGetSymbolAddress((void**)&gk, g_k);
    cudaGetSymbolAddress((void**)&gv, g_v);

    __half *hsh, *hsl, *wqh, *wql, *wkh, *wkl, *wvh, *woh, *ath, *atl;
    __half *qh, *ql, *kh, *kl, *vh;
    cudaGetSymbolAddress((void**)&hsh, g_hs_h); cudaGetSymbolAddress((void**)&hsl, g_hs_l);
    cudaGetSymbolAddress((void**)&wqh, g_wq_h); cudaGetSymbolAddress((void**)&wql, g_wq_l);
    cudaGetSymbolAddress((void**)&wkh, g_wk_h); cudaGetSymbolAddress((void**)&wkl, g_wk_l);
    cudaGetSymbolAddress((void**)&wvh, g_wv_h);
    cudaGetSymbolAddress((void**)&woh, g_wo_h);
    cudaGetSymbolAddress((void**)&ath, g_at_h); cudaGetSymbolAddress((void**)&atl, g_at_l);
    cudaGetSymbolAddress((void**)&qh, g_qh);    cudaGetSymbolAddress((void**)&ql, g_ql);
    cudaGetSymbolAddress((void**)&kh, g_kh);    cudaGetSymbolAddress((void**)&kl, g_kl);
    cudaGetSymbolAddress((void**)&vh, g_vh);

    cudaFuncSetAttribute(gemm_qkv_kernel, cudaFuncAttributeMaxDynamicSharedMemorySize,
                         GEMM_SMEM_BYTES);
    cudaFuncSetAttribute(gemm_wo_kernel, cudaFuncAttributeMaxDynamicSharedMemorySize,
                         GEMM_SMEM_BYTES);
    cudaFuncSetAttribute(attn_tc_kernel, cudaFuncAttributeMaxDynamicSharedMemorySize,
                         ATT_SM_BYTES);

    // all splits in one launch
    split_all_kernel<<<20480, 256>>>(hs, wq, wk, wv, wo,
                                     hsh, hsl, wqh, wql, wkh, wkl, wvh, woh);

    // fused QKV projections (compile-time pass dispatch)
    gemm_qkv_kernel<<<dim3(32, S / 128), 256, GEMM_SMEM_BYTES>>>(
        hsh, hsl, wqh, wql, wkh, wkl, wvh, gq, gk, gv);

    // RMSNorm + RoPE
    norm_rope_kernel<<<S * 16 / 8, 256>>>(gq, gk, gv, cosp, sinp, qw, kw,
                                          qh, ql, kh, kl, vh);

    // attention (64-q tiles, 2 CTAs/SM)
    attn_tc_kernel<<<dim3(S / 64, NH), 128, ATT_SM_BYTES>>>(
        qh, ql, kh, kl, vh, ath, atl);

    // output projection (2-pass)
    gemm_wo_kernel<<<dim3(HID / 128, S / 128), 256, GEMM_SMEM_BYTES>>>(
        ath, atl, woh, out);
}

// round 11
// speedup vs baseline: 3.9856x; 1.1884x over previous
#include <cuda_runtime.h>
#include <cuda_fp16.h>
#include <math.h>
#include <stdint.h>

// ---------------- problem constants ----------------
#define S     2048
#define HID   2560
#define NH    8
#define NKV   4
#define DH    256
#define WIN   1024
#define QN    (NH*DH)    // 2048
#define KVN   (NKV*DH)   // 1024

// ---------------- scratch ----------------
__device__ float g_q[S * QN];
__device__ float g_k[S * KVN];
__device__ float g_v[S * KVN];

__device__ __half g_hs_h[S * HID],  g_hs_l[S * HID];
__device__ __half g_wq_h[HID * QN], g_wq_l[HID * QN];
__device__ __half g_wk_h[HID * KVN], g_wk_l[HID * KVN];
__device__ __half g_wv_h[HID * KVN];
__device__ __half g_wo_h[QN * HID];
__device__ __half g_at_h[S * QN],   g_at_l[S * QN];

__device__ __half g_qh[S * QN],  g_ql[S * QN];
__device__ __half g_kh[S * KVN], g_kl[S * KVN];
__device__ __half g_vh[S * KVN];

// ---------------- PTX helpers ----------------
#define CP16(dst_u32, src_ptr) \
    asm volatile("cp.async.cg.shared.global [%0], [%1], 16;\n" :: "r"(dst_u32), "l"(src_ptr))
#define CP_COMMIT()  asm volatile("cp.async.commit_group;\n")
#define CP_WAIT0()   asm volatile("cp.async.wait_group 0;\n" ::: "memory")

#define LDSM4(R, addr) \
    asm volatile("ldmatrix.sync.aligned.m8n8.x4.shared.b16 {%0,%1,%2,%3}, [%4];\n" \
        : "=r"((R)[0]), "=r"((R)[1]), "=r"((R)[2]), "=r"((R)[3]) : "r"(addr))
#define LDSM4T(R, addr) \
    asm volatile("ldmatrix.sync.aligned.m8n8.x4.trans.shared.b16 {%0,%1,%2,%3}, [%4];\n" \
        : "=r"((R)[0]), "=r"((R)[1]), "=r"((R)[2]), "=r"((R)[3]) : "r"(addr))

#define MMA_FP16(d, a, b0, b1) \
    asm volatile("mma.sync.aligned.m16n8k16.row.col.f32.f16.f16.f32 " \
        "{%0,%1,%2,%3},{%4,%5,%6,%7},{%8,%9},{%0,%1,%2,%3};\n" \
        : "+f"((d)[0]), "+f"((d)[1]), "+f"((d)[2]), "+f"((d)[3]) \
        : "r"((a)[0]), "r"((a)[1]), "r"((a)[2]), "r"((a)[3]), "r"(b0), "r"(b1))

#define MMA_F16A(d, a, b0, b1) \
    asm volatile("mma.sync.aligned.m16n8k16.row.col.f16.f16.f16.f16 " \
        "{%0,%1},{%2,%3,%4,%5},{%6,%7},{%0,%1};\n" \
        : "+r"((d)[0]), "+r"((d)[1]) \
        : "r"((a)[0]), "r"((a)[1]), "r"((a)[2]), "r"((a)[3]), "r"(b0), "r"(b1))

__device__ __forceinline__ uint32_t smem_u32(const void* p) {
    return (uint32_t)__cvta_generic_to_shared(p);
}
__device__ __forceinline__ void add_h2(float* f01, uint32_t packed) {
    __half2 h = *(__half2*)&packed;
    float2 v = __half22float2(h);
    f01[0] += v.x; f01[1] += v.y;
}
// XOR swizzle for 512B rows
__device__ __forceinline__ uint32_t swz(int row, int cb) {
    return (uint32_t)(row * 512 + ((cb ^ (row & 7)) << 4));
}

// =====================================================================
// Fused split kernel (one launch)
// =====================================================================
__global__ __launch_bounds__(256) void split_all_kernel(
    const float* __restrict__ hs, const float* __restrict__ wq,
    const float* __restrict__ wk, const float* __restrict__ wv,
    const float* __restrict__ wo,
    __half* __restrict__ hsh, __half* __restrict__ hsl,
    __half* __restrict__ wqh, __half* __restrict__ wql,
    __half* __restrict__ wkh, __half* __restrict__ wkl,
    __half* __restrict__ wvh, __half* __restrict__ woh)
{
    int b = blockIdx.x;
    const float* x; __half *h, *l;
    if (b < 5120)       { x = hs; h = hsh; l = hsl; }
    else if (b < 10240) { x = wq; h = wqh; l = wql; b -= 5120; }
    else if (b < 12800) { x = wk; h = wkh; l = wkl; b -= 10240; }
    else if (b < 15360) { x = wv; h = wvh; l = nullptr; b -= 12800; }
    else                { x = wo; h = woh; l = nullptr; b -= 15360; }

    int i = (b * 256 + threadIdx.x) * 4;
    float4 v = *(const float4*)(x + i);
    __half h0 = __float2half_rn(v.x), h1 = __float2half_rn(v.y);
    __half h2 = __float2half_rn(v.z), h3 = __float2half_rn(v.w);
    *(__half2*)(h + i)     = __halves2half2(h0, h1);
    *(__half2*)(h + i + 2) = __halves2half2(h2, h3);
    if (l) {
        *(__half2*)(l + i)     = __halves2half2(
            __float2half_rn(v.x - __half2float(h0)), __float2half_rn(v.y - __half2float(h1)));
        *(__half2*)(l + i + 2) = __halves2half2(
            __float2half_rn(v.z - __half2float(h2)), __float2half_rn(v.w - __half2float(h3)));
    }
}

// =====================================================================
// fp16 TC GEMM body — PASSES and MI (M-tile = 32*MI rows) compile-time.
// hi pass f32-acc + cross passes f16-acc. (32*MI)x128x32 tile, 8 warps.
// =====================================================================
#define AS_STR 40
#define BS_STR 136
#define BBUF   (32 * BS_STR)

template <int PASSES, int MI>
__device__ __forceinline__ void gemm_body(
    const __half* __restrict__ Ah, const __half* __restrict__ Al,
    const __half* __restrict__ Bh, const __half* __restrict__ Bl,
    float* __restrict__ C, int N, int K, int m0, int n0,
    __half* smbuf)
{
    constexpr int AROWS  = MI * 32;
    constexpr int ABUF_E = AROWS * AS_STR;
    constexpr int BUF_E  = 2 * ABUF_E + 2 * BBUF;

    const int t    = threadIdx.x;
    const int lane = t & 31;
    const int wid  = t >> 5;
    const int wm   = wid >> 2;           // 0..1, slab of 16*MI rows
    const int wn   = wid & 3;

    float acc[MI][4][4];
    uint32_t accL[MI][4][2];
#pragma unroll
    for (int mi = 0; mi < MI; mi++)
#pragma unroll
        for (int ni = 0; ni < 4; ni++) {
#pragma unroll
            for (int r = 0; r < 4; r++) acc[mi][ni][r] = 0.f;
            accL[mi][ni][0] = 0u; accL[mi][ni][1] = 0u;
        }

    uint32_t sbase[2][4];
#pragma unroll
    for (int b = 0; b < 2; b++) {
        __half* p = smbuf + b * BUF_E;
        sbase[b][0] = smem_u32(p);
        sbase[b][1] = smem_u32(p + ABUF_E);
        sbase[b][2] = smem_u32(p + 2 * ABUF_E);
        sbase[b][3] = smem_u32(p + 2 * ABUF_E + BBUF);
    }

    auto issue = [&](int k0, int buf) {
#pragma unroll
        for (int p = 0; p < 2; p++) {
            int id = t + p * 256;
            if (AROWS == 128 || p == 0) {          // A needs AROWS*4 cp16s
                int am = id >> 2, ac = (id & 3) * 8;
                size_t aoff = (size_t)(m0 + am) * K + k0 + ac;
                uint32_t ad = (uint32_t)(am * AS_STR + ac) * 2;
                CP16(sbase[buf][0] + ad, Ah + aoff);
                CP16(sbase[buf][1] + ad, Al + aoff);
            }
            int bk = id >> 4, bc = (id & 15) * 8;
            size_t boff = (size_t)(k0 + bk) * N + n0 + bc;
            uint32_t bd = (uint32_t)(bk * BS_STR + bc) * 2;
            CP16(sbase[buf][2] + bd, Bh + boff);
            if (PASSES == 3) CP16(sbase[buf][3] + bd, Bl + boff);
        }
        CP_COMMIT();
    };

    issue(0, 0);
    const int nIter = K / 32;

    for (int it = 0; it < nIter; it++) {
        CP_WAIT0();
        __syncthreads();
        if (it + 1 < nIter) issue((it + 1) * 32, (it + 1) & 1);

        const int buf = it & 1;
        const uint32_t ah_s = sbase[buf][0];
        const uint32_t al_s = sbase[buf][1];
        const uint32_t bh_s = sbase[buf][2];
        const uint32_t bl_s = sbase[buf][3];

#pragma unroll
        for (int ks = 0; ks < 32; ks += 16) {
            uint32_t fah[MI][4], fal[MI][4], fbh[2][4], fbl[2][4];

            int arow = lane & 15;
            int acol = ks + ((lane >> 4) & 1) * 8;
#pragma unroll
            for (int mi = 0; mi < MI; mi++) {
                uint32_t off = (uint32_t)((wm * 16 * MI + mi * 16 + arow) * AS_STR + acol) * 2;
                LDSM4(fah[mi], ah_s + off);
                LDSM4(fal[mi], al_s + off);
            }

            int bkrow = ks + (lane & 7) + ((lane >> 3) & 1) * 8;
#pragma unroll
            for (int np = 0; np < 2; np++) {
                int bcol = wn * 32 + np * 16 + ((lane >> 4) & 1) * 8;
                uint32_t off = (uint32_t)(bkrow * BS_STR + bcol) * 2;
                LDSM4T(fbh[np], bh_s + off);
                if (PASSES == 3) LDSM4T(fbl[np], bl_s + off);
            }

#pragma unroll
            for (int mi = 0; mi < MI; mi++)
#pragma unroll
                for (int ni = 0; ni < 4; ni++) {
                    const uint32_t* bh2 = &fbh[ni >> 1][(ni & 1) * 2];
                    MMA_FP16(acc[mi][ni], fah[mi], bh2[0], bh2[1]);
                    MMA_F16A(accL[mi][ni], fal[mi], bh2[0], bh2[1]);
                    if (PASSES == 3) {
                        const uint32_t* bl2 = &fbl[ni >> 1][(ni & 1) * 2];
                        MMA_F16A(accL[mi][ni], fah[mi], bl2[0], bl2[1]);
                    }
                }
        }
        __syncthreads();
    }

    int g  = lane >> 2;
    int c2 = (lane & 3) * 2;
#pragma unroll
    for (int mi = 0; mi < MI; mi++)
#pragma unroll
        for (int ni = 0; ni < 4; ni++) {
            add_h2(&acc[mi][ni][0], accL[mi][ni][0]);
            add_h2(&acc[mi][ni][2], accL[mi][ni][1]);
            int row = m0 + wm * 16 * MI + mi * 16 + g;
            int col = n0 + wn * 32 + ni * 8 + c2;
            *(float2*)(C + (size_t)row * N + col)       = make_float2(acc[mi][ni][0], acc[mi][ni][1]);
            *(float2*)(C + (size_t)(row + 8) * N + col) = make_float2(acc[mi][ni][2], acc[mi][ni][3]);
        }
}

// smem for MI=2 tiles
#define GEMM64_BUF_E (2 * (64 * AS_STR) + 2 * BBUF)
#define GEMM64_SMEM  (2 * GEMM64_BUF_E * 2)

// fused QKV projection — 64-row M tiles, grid (32, S/64)
__global__ __launch_bounds__(256) void gemm_qkv_kernel(
    const __half* __restrict__ Ah, const __half* __restrict__ Al,
    const __half* __restrict__ wqh, const __half* __restrict__ wql,
    const __half* __restrict__ wkh, const __half* __restrict__ wkl,
    const __half* __restrict__ wvh,
    float* __restrict__ gq, float* __restrict__ gk, float* __restrict__ gv)
{
    extern __shared__ __half smbuf[];
    const int bx = blockIdx.x;
    const int m0 = blockIdx.y * 64;
    if (bx < 16)
        gemm_body<3, 2>(Ah, Al, wqh, wql, gq, QN, HID, m0, bx * 128, smbuf);
    else if (bx < 24)
        gemm_body<3, 2>(Ah, Al, wkh, wkl, gk, KVN, HID, m0, (bx - 16) * 128, smbuf);
    else
        gemm_body<2, 2>(Ah, Al, wvh, wvh, gv, KVN, HID, m0, (bx - 24) * 128, smbuf);
}

// output projection — 64-row M tiles, grid (HID/128, S/64)
__global__ __launch_bounds__(256) void gemm_wo_kernel(
    const __half* __restrict__ Ah, const __half* __restrict__ Al,
    const __half* __restrict__ Bh, float* __restrict__ C)
{
    extern __shared__ __half smbuf[];
    gemm_body<2, 2>(Ah, Al, Bh, Bh, C, HID, QN, blockIdx.y * 64, blockIdx.x * 128, smbuf);
}

// =====================================================================
// Fused RMSNorm (+weight) + RoPE — warp-per-head (unchanged)
// =====================================================================
__global__ __launch_bounds__(256) void norm_rope_kernel(
    const float* __restrict__ q, const float* __restrict__ k, const float* __restrict__ v,
    const float* __restrict__ cosp, const float* __restrict__ sinp,
    const float* __restrict__ qw, const float* __restrict__ kw,
    __half* __restrict__ qh, __half* __restrict__ ql,
    __half* __restrict__ kh, __half* __restrict__ kl,
    __half* __restrict__ vh)
{
    const int lane = threadIdx.x & 31;
    const int row  = blockIdx.x * 8 + (threadIdx.x >> 5);
    const int s    = row >> 4;
    const int idx  = row & 15;

    const float* base;
    const float* w;
    __half *oh, *ol;
    bool rope;
    if (idx < 8) {
        base = q + (size_t)s * QN + idx * DH; w = qw; rope = true;
        oh = qh + (size_t)s * QN + idx * DH; ol = ql + (size_t)s * QN + idx * DH;
    } else if (idx < 12) {
        base = k + (size_t)s * KVN + (idx - 8) * DH; w = kw; rope = true;
        oh = kh + (size_t)s * KVN + (idx - 8) * DH; ol = kl + (size_t)s * KVN + (idx - 8) * DH;
    } else {
        base = v + (size_t)s * KVN + (idx - 12) * DH; w = nullptr; rope = false;
        oh = vh + (size_t)s * KVN + (idx - 12) * DH; ol = nullptr;
    }

    const int d0 = lane * 8;
    float x[8];
    *(float4*)&x[0] = *(const float4*)(base + d0);
    *(float4*)&x[4] = *(const float4*)(base + d0 + 4);

    float ss = 0.f;
#pragma unroll
    for (int j = 0; j < 8; j++) ss += x[j] * x[j];
#pragma unroll
    for (int o = 16; o; o >>= 1) ss += __shfl_xor_sync(0xffffffffu, ss, o);

    float inv = rsqrtf(ss * (1.0f / 256.0f) + 1e-6f);
    float y[8];
#pragma unroll
    for (int j = 0; j < 8; j++) y[j] = x[j] * inv;
    if (w) {
        float wv[8];
        *(float4*)&wv[0] = *(const float4*)(w + d0);
        *(float4*)&wv[4] = *(const float4*)(w + d0 + 4);
#pragma unroll
        for (int j = 0; j < 8; j++) y[j] *= wv[j];
    }

    float out[8];
    if (rope) {
        float c[8], si[8];
        *(float4*)&c[0]  = *(const float4*)(cosp + (size_t)s * DH + d0);
        *(float4*)&c[4]  = *(const float4*)(cosp + (size_t)s * DH + d0 + 4);
        *(float4*)&si[0] = *(const float4*)(sinp + (size_t)s * DH + d0);
        *(float4*)&si[4] = *(const float4*)(sinp + (size_t)s * DH + d0 + 4);
#pragma unroll
        for (int j = 0; j < 8; j++) {
            float pv = __shfl_xor_sync(0xffffffffu, y[j], 16);
            float rh = (lane < 16) ? -pv : pv;
            out[j] = y[j] * c[j] + rh * si[j];
        }
    } else {
#pragma unroll
        for (int j = 0; j < 8; j++) out[j] = y[j];
    }

    __half hi8[8], lo8[8];
#pragma unroll
    for (int j = 0; j < 8; j++) {
        hi8[j] = __float2half_rn(out[j]);
        lo8[j] = __float2half_rn(out[j] - __half2float(hi8[j]));
    }
    *(uint4*)(oh + d0) = *(uint4*)hi8;
    if (ol) *(uint4*)(ol + d0) = *(uint4*)lo8;
}

// =====================================================================
// TC flash attention: 64-q tiles, 4 warps. QK 3-pass; PV SINGLE-pass
// (P quantized to one fp16 — post-softmax linear path, low error).
// =====================================================================
#define ATT_SM_BYTES (2 * 64 * 512 + 3 * 32 * 512)   // 114688

__global__ __launch_bounds__(128, 2) void attn_tc_kernel(
    const __half* __restrict__ Qh, const __half* __restrict__ Ql,
    const __half* __restrict__ Kh, const __half* __restrict__ Kl,
    const __half* __restrict__ Vh,
    __half* __restrict__ Oh, __half* __restrict__ Ol)
{
    extern __shared__ __half sm2[];
    const int t    = threadIdx.x;
    const int lane = t & 31;
    const int w    = t >> 5;
    const int q0   = blockIdx.x * 64;
    const int h    = blockIdx.y;
    const int kvh  = h >> 1;

    const uint32_t sQh = smem_u32(sm2);
    const uint32_t sQl = sQh + 64 * 512;
    const uint32_t sKh = sQl + 64 * 512;
    const uint32_t sKl = sKh + 32 * 512;
    const uint32_t sVh = sKl + 32 * 512;

    // ---- Q load ----
    const __half* gqh = Qh + (size_t)q0 * QN + h * DH;
    const __half* gql = Ql + (size_t)q0 * QN + h * DH;
#pragma unroll
    for (int it = 0; it < 16; it++) {
        int id = t + it * 128;
        int row = id >> 5, cb = id & 31;
        uint32_t d = swz(row, cb);
        size_t g = (size_t)row * QN + cb * 8;
        CP16(sQh + d, gqh + g);
        CP16(sQl + d, gql + g);
    }
    CP_COMMIT();

    auto issueKV = [&](int k0) {
        const __half* gkh = Kh + (size_t)k0 * KVN + kvh * DH;
        const __half* gkl = Kl + (size_t)k0 * KVN + kvh * DH;
        const __half* gvh = Vh + (size_t)k0 * KVN + kvh * DH;
#pragma unroll
        for (int it = 0; it < 8; it++) {
            int id = t + it * 128;
            int row = id >> 5, cb = id & 31;
            uint32_t d = swz(row, cb);
            size_t g = (size_t)row * KVN + cb * 8;
            CP16(sKh + d, gkh + g);
            CP16(sKl + d, gkl + g);
            CP16(sVh + d, gvh + g);
        }
        CP_COMMIT();
    };

    float o[32][4];
#pragma unroll
    for (int dt = 0; dt < 32; dt++)
#pragma unroll
        for (int r = 0; r < 4; r++) o[dt][r] = 0.f;
    float mrow[2] = {-1e30f, -1e30f};
    float lrow[2] = {0.f, 0.f};

    const int kb_lo = max(0, q0 - (WIN - 1)) >> 5;
    const int kb_hi = (q0 + 63) >> 5;
    const int qw_lo = q0 + w * 16;
    const int gq_row = lane >> 2;
    const int t4 = lane & 3;

    issueKV(kb_lo * 32);

    for (int kb = kb_lo; kb <= kb_hi; kb++) {
        CP_WAIT0();
        __syncthreads();

        const int k0 = kb * 32;
        bool active = (k0 <= qw_lo + 15) && (k0 + 31 >= qw_lo - (WIN - 1));
        if (active) {
            float s[4][4];
            uint32_t sl[4][2];
#pragma unroll
            for (int tl = 0; tl < 4; tl++) {
#pragma unroll
                for (int r = 0; r < 4; r++) s[tl][r] = 0.f;
                sl[tl][0] = 0u; sl[tl][1] = 0u;
            }

#pragma unroll
            for (int dc = 0; dc < 16; dc++) {
                uint32_t qa[4], qb[4], k1h[4], k2h[4], k1l[4], k2l[4];
                int cb = dc * 2 + (lane >> 4);
                uint32_t qoff = swz(w * 16 + (lane & 15), cb);
                LDSM4(qa, sQh + qoff);
                LDSM4(qb, sQl + qoff);
                uint32_t koff = swz(lane & 15, cb);
                LDSM4(k1h, sKh + koff);
                LDSM4(k2h, sKh + koff + 16 * 512);
                LDSM4(k1l, sKl + koff);
                LDSM4(k2l, sKl + koff + 16 * 512);

                MMA_FP16(s[0], qa, k1h[0], k1h[2]);
                MMA_FP16(s[1], qa, k1h[1], k1h[3]);
                MMA_FP16(s[2], qa, k2h[0], k2h[2]);
                MMA_FP16(s[3], qa, k2h[1], k2h[3]);
                MMA_F16A(sl[0], qa, k1l[0], k1l[2]);
                MMA_F16A(sl[1], qa, k1l[1], k1l[3]);
                MMA_F16A(sl[2], qa, k2l[0], k2l[2]);
                MMA_F16A(sl[3], qa, k2l[1], k2l[3]);
                MMA_F16A(sl[0], qb, k1h[0], k1h[2]);
                MMA_F16A(sl[1], qb, k1h[1], k1h[3]);
                MMA_F16A(sl[2], qb, k2h[0], k2h[2]);
                MMA_F16A(sl[3], qb, k2h[1], k2h[3]);
            }
#pragma unroll
            for (int tl = 0; tl < 4; tl++) {
                add_h2(&s[tl][0], sl[tl][0]);
                add_h2(&s[tl][2], sl[tl][1]);
            }

            float corr[2];
#pragma unroll
            for (int r = 0; r < 2; r++) {
                int qg = qw_lo + gq_row + r * 8;
                float mx = -1e30f;
#pragma unroll
                for (int tl = 0; tl < 4; tl++) {
#pragma unroll
                    for (int c = 0; c < 2; c++) {
                        int kg = k0 + tl * 8 + 2 * t4 + c;
                        bool ok = (kg <= qg) && (qg - kg < WIN);
                        if (!ok) s[tl][r * 2 + c] = -1e30f;
                        mx = fmaxf(mx, s[tl][r * 2 + c]);
                    }
                }
                mx = fmaxf(mx, __shfl_xor_sync(0xffffffffu, mx, 1));
                mx = fmaxf(mx, __shfl_xor_sync(0xffffffffu, mx, 2));
                float m_new = fmaxf(mrow[r], mx);
                float mexp = (m_new <= -1e29f) ? 0.f : m_new;
                float sum = 0.f;
#pragma unroll
                for (int tl = 0; tl < 4; tl++) {
#pragma unroll
                    for (int c = 0; c < 2; c++) {
                        float p = __expf(s[tl][r * 2 + c] - mexp);
                        s[tl][r * 2 + c] = p;
                        sum += p;
                    }
                }
                sum += __shfl_xor_sync(0xffffffffu, sum, 1);
                sum += __shfl_xor_sync(0xffffffffu, sum, 2);
                corr[r] = __expf(mrow[r] - m_new);
                mrow[r] = m_new;
                lrow[r] = lrow[r] * corr[r] + sum;
            }

            // P -> single fp16 A-fragments (post-softmax, no amplification)
            uint32_t ph[2][4];
#pragma unroll
            for (int kc = 0; kc < 2; kc++) {
#pragma unroll
                for (int r2 = 0; r2 < 4; r2++) {
                    int tl = kc * 2 + (r2 >> 1);
                    int r  = r2 & 1;
                    __half2 hh = __halves2half2(__float2half_rn(s[tl][r * 2 + 0]),
                                                __float2half_rn(s[tl][r * 2 + 1]));
                    ph[kc][r2] = *(uint32_t*)&hh;
                }
            }

#pragma unroll
            for (int dt = 0; dt < 32; dt++) {
                o[dt][0] *= corr[0]; o[dt][1] *= corr[0];
                o[dt][2] *= corr[1]; o[dt][3] *= corr[1];
            }

#pragma unroll
            for (int dg = 0; dg < 16; dg++) {
#pragma unroll
                for (int kc = 0; kc < 2; kc++) {
                    uint32_t vh4[4];
                    int row_v = kc * 16 + (lane & 7) + ((lane >> 3) & 1) * 8;
                    int cb_v  = dg * 2 + ((lane >> 4) & 1);
                    LDSM4T(vh4, sVh + swz(row_v, cb_v));
                    MMA_FP16(o[2 * dg],     ph[kc], vh4[0], vh4[1]);
                    MMA_FP16(o[2 * dg + 1], ph[kc], vh4[2], vh4[3]);
                }
            }
        }
        __syncthreads();
        if (kb < kb_hi) issueKV((kb + 1) * 32);
    }

    // finalize -> fp16 hi/lo output (A operand of wo GEMM)
    float inv0 = 1.f / lrow[0];
    float inv1 = 1.f / lrow[1];
    size_t r0 = (size_t)(q0 + w * 16 + gq_row) * QN + h * DH;
    size_t r1 = r0 + (size_t)8 * QN;
#pragma unroll
    for (int dt = 0; dt < 32; dt++) {
        int col = dt * 8 + 2 * t4;
        float a0 = o[dt][0] * inv0, a1 = o[dt][1] * inv0;
        float b0 = o[dt][2] * inv1, b1 = o[dt][3] * inv1;
        __half ha0 = __float2half_rn(a0), ha1 = __float2half_rn(a1);
        __half hb0 = __float2half_rn(b0), hb1 = __float2half_rn(b1);
        *(__half2*)(Oh + r0 + col) = __halves2half2(ha0, ha1);
        *(__half2*)(Oh + r1 + col) = __halves2half2(hb0, hb1);
        *(__half2*)(Ol + r0 + col) = __halves2half2(
            __float2half_rn(a0 - __half2float(ha0)), __float2half_rn(a1 - __half2float(ha1)));
        *(__half2*)(Ol + r1 + col) = __halves2half2(
            __float2half_rn(b0 - __half2float(hb0)), __float2half_rn(b1 - __half2float(hb1)));
    }
}

// =====================================================================
// kernel_launch
// =====================================================================
extern "C" void kernel_launch(void* const* d_in, const int* in_sizes, int n_in,
                              void* d_out, int out_size)
{
    const float* hs   = (const float*)d_in[0];
    const float* cosp = (const float*)d_in[1];
    const float* sinp = (const float*)d_in[2];
    const float* wq   = (const float*)d_in[3];
    const float* wk   = (const float*)d_in[4];
    const float* wv   = (const float*)d_in[5];
    const float* wo   = (const float*)d_in[6];
    const float* qw   = (const float*)d_in[7];
    const float* kw   = (const float*)d_in[8];
    float* out = (float*)d_out;

    float *gq, *gk, *gv;
    cudaGetSymbolAddress((void**)&gq, g_q);
    cudaGetSymbolAddress((void**)&gk, g_k);
    cudaGetSymbolAddress((void**)&gv, g_v);

    __half *hsh, *hsl, *wqh, *wql, *wkh, *wkl, *wvh, *woh, *ath, *atl;
    __half *qh, *ql, *kh, *kl, *vh;
    cudaGetSymbolAddress((void**)&hsh, g_hs_h); cudaGetSymbolAddress((void**)&hsl, g_hs_l);
    cudaGetSymbolAddress((void**)&wqh, g_wq_h); cudaGetSymbolAddress((void**)&wql, g_wq_l);
    cudaGetSymbolAddress((void**)&wkh, g_wk_h); cudaGetSymbolAddress((void**)&wkl, g_wk_l);
    cudaGetSymbolAddress((void**)&wvh, g_wv_h);
    cudaGetSymbolAddress((void**)&woh, g_wo_h);
    cudaGetSymbolAddress((void**)&ath, g_at_h); cudaGetSymbolAddress((void**)&atl, g_at_l);
    cudaGetSymbolAddress((void**)&qh, g_qh);    cudaGetSymbolAddress((void**)&ql, g_ql);
    cudaGetSymbolAddress((void**)&kh, g_kh);    cudaGetSymbolAddress((void**)&kl, g_kl);
    cudaGetSymbolAddress((void**)&vh, g_vh);

    cudaFuncSetAttribute(gemm_qkv_kernel, cudaFuncAttributeMaxDynamicSharedMemorySize,
                         GEMM64_SMEM);
    cudaFuncSetAttribute(gemm_wo_kernel, cudaFuncAttributeMaxDynamicSharedMemorySize,
                         GEMM64_SMEM);
    cudaFuncSetAttribute(attn_tc_kernel, cudaFuncAttributeMaxDynamicSharedMemorySize,
                         ATT_SM_BYTES);

    // all splits in one launch
    split_all_kernel<<<20480, 256>>>(hs, wq, wk, wv, wo,
                                     hsh, hsl, wqh, wql, wkh, wkl, wvh, woh);

    // fused QKV projections — 64-row M tiles (1024 CTAs)
    gemm_qkv_kernel<<<dim3(32, S / 64), 256, GEMM64_SMEM>>>(
        hsh, hsl, wqh, wql, wkh, wkl, wvh, gq, gk, gv);

    // RMSNorm + RoPE
    norm_rope_kernel<<<S * 16 / 8, 256>>>(gq, gk, gv, cosp, sinp, qw, kw,
                                          qh, ql, kh, kl, vh);

    // attention (64-q tiles, PV single-pass)
    attn_tc_kernel<<<dim3(S / 64, NH), 128, ATT_SM_BYTES>>>(
        qh, ql, kh, kl, vh, ath, atl);

    // output projection — 64-row M tiles (640 CTAs)
    gemm_wo_kernel<<<dim3(HID / 128, S / 64), 256, GEMM64_SMEM>>>(
        ath, atl, woh, out);
}

// round 12
// speedup vs baseline: 4.4783x; 1.1236x over previous
#include <cuda_runtime.h>
#include <cuda_fp16.h>
#include <math.h>
#include <stdint.h>

// ---------------- problem constants ----------------
#define S     2048
#define HID   2560
#define NH    8
#define NKV   4
#define DH    256
#define WIN   1024
#define QN    (NH*DH)    // 2048
#define KVN   (NKV*DH)   // 1024

// ---------------- scratch ----------------
__device__ float g_q[S * QN];
__device__ float g_k[S * KVN];
__device__ float g_v[S * KVN];

__device__ __half g_hs_h[S * HID],  g_hs_l[S * HID];
__device__ __half g_wq_h[HID * QN], g_wq_l[HID * QN];
__device__ __half g_wk_h[HID * KVN], g_wk_l[HID * KVN];
__device__ __half g_wv_h[HID * KVN];
__device__ __half g_wo_h[QN * HID];
__device__ __half g_at_h[S * QN];

__device__ __half g_qh[S * QN],  g_ql[S * QN];
__device__ __half g_kh[S * KVN], g_kl[S * KVN];
__device__ __half g_vh[S * KVN];

// ---------------- PTX helpers ----------------
#define CP16(dst_u32, src_ptr) \
    asm volatile("cp.async.cg.shared.global [%0], [%1], 16;\n" :: "r"(dst_u32), "l"(src_ptr))
#define CP_COMMIT()  asm volatile("cp.async.commit_group;\n")
#define CP_WAIT0()   asm volatile("cp.async.wait_group 0;\n" ::: "memory")

#define LDSM4(R, addr) \
    asm volatile("ldmatrix.sync.aligned.m8n8.x4.shared.b16 {%0,%1,%2,%3}, [%4];\n" \
        : "=r"((R)[0]), "=r"((R)[1]), "=r"((R)[2]), "=r"((R)[3]) : "r"(addr))
#define LDSM4T(R, addr) \
    asm volatile("ldmatrix.sync.aligned.m8n8.x4.trans.shared.b16 {%0,%1,%2,%3}, [%4];\n" \
        : "=r"((R)[0]), "=r"((R)[1]), "=r"((R)[2]), "=r"((R)[3]) : "r"(addr))

#define MMA_FP16(d, a, b0, b1) \
    asm volatile("mma.sync.aligned.m16n8k16.row.col.f32.f16.f16.f32 " \
        "{%0,%1,%2,%3},{%4,%5,%6,%7},{%8,%9},{%0,%1,%2,%3};\n" \
        : "+f"((d)[0]), "+f"((d)[1]), "+f"((d)[2]), "+f"((d)[3]) \
        : "r"((a)[0]), "r"((a)[1]), "r"((a)[2]), "r"((a)[3]), "r"(b0), "r"(b1))

#define MMA_F16A(d, a, b0, b1) \
    asm volatile("mma.sync.aligned.m16n8k16.row.col.f16.f16.f16.f16 " \
        "{%0,%1},{%2,%3,%4,%5},{%6,%7},{%0,%1};\n" \
        : "+r"((d)[0]), "+r"((d)[1]) \
        : "r"((a)[0]), "r"((a)[1]), "r"((a)[2]), "r"((a)[3]), "r"(b0), "r"(b1))

__device__ __forceinline__ uint32_t smem_u32(const void* p) {
    return (uint32_t)__cvta_generic_to_shared(p);
}
__device__ __forceinline__ void add_h2(float* f01, uint32_t packed) {
    __half2 h = *(__half2*)&packed;
    float2 v = __half22float2(h);
    f01[0] += v.x; f01[1] += v.y;
}
// XOR swizzle for 512B rows
__device__ __forceinline__ uint32_t swz(int row, int cb) {
    return (uint32_t)(row * 512 + ((cb ^ (row & 7)) << 4));
}

// =====================================================================
// Fused split kernel (one launch)
// =====================================================================
__global__ __launch_bounds__(256) void split_all_kernel(
    const float* __restrict__ hs, const float* __restrict__ wq,
    const float* __restrict__ wk, const float* __restrict__ wv,
    const float* __restrict__ wo,
    __half* __restrict__ hsh, __half* __restrict__ hsl,
    __half* __restrict__ wqh, __half* __restrict__ wql,
    __half* __restrict__ wkh, __half* __restrict__ wkl,
    __half* __restrict__ wvh, __half* __restrict__ woh)
{
    int b = blockIdx.x;
    const float* x; __half *h, *l;
    if (b < 5120)       { x = hs; h = hsh; l = hsl; }
    else if (b < 10240) { x = wq; h = wqh; l = wql; b -= 5120; }
    else if (b < 12800) { x = wk; h = wkh; l = wkl; b -= 10240; }
    else if (b < 15360) { x = wv; h = wvh; l = nullptr; b -= 12800; }
    else                { x = wo; h = woh; l = nullptr; b -= 15360; }

    int i = (b * 256 + threadIdx.x) * 4;
    float4 v = *(const float4*)(x + i);
    __half h0 = __float2half_rn(v.x), h1 = __float2half_rn(v.y);
    __half h2 = __float2half_rn(v.z), h3 = __float2half_rn(v.w);
    *(__half2*)(h + i)     = __halves2half2(h0, h1);
    *(__half2*)(h + i + 2) = __halves2half2(h2, h3);
    if (l) {
        *(__half2*)(l + i)     = __halves2half2(
            __float2half_rn(v.x - __half2float(h0)), __float2half_rn(v.y - __half2float(h1)));
        *(__half2*)(l + i + 2) = __halves2half2(
            __float2half_rn(v.z - __half2float(h2)), __float2half_rn(v.w - __half2float(h3)));
    }
}

// =====================================================================
// fp16 TC GEMM body — PASSES/MI compile-time.
//  PASSES=1: C = Ah*Bh (f32acc)
//  PASSES=2: += Al*Bh (f16acc)
//  PASSES=3: += Ah*Bl (f16acc)
// =====================================================================
#define AS_STR 40
#define BS_STR 136
#define BBUF   (32 * BS_STR)

template <int PASSES, int MI>
__device__ __forceinline__ void gemm_body(
    const __half* __restrict__ Ah, const __half* __restrict__ Al,
    const __half* __restrict__ Bh, const __half* __restrict__ Bl,
    float* __restrict__ C, int N, int K, int m0, int n0,
    __half* smbuf)
{
    constexpr int AROWS  = MI * 32;
    constexpr int ABUF_E = AROWS * AS_STR;
    constexpr int BUF_E  = 2 * ABUF_E + 2 * BBUF;

    const int t    = threadIdx.x;
    const int lane = t & 31;
    const int wid  = t >> 5;
    const int wm   = wid >> 2;
    const int wn   = wid & 3;

    float acc[MI][4][4];
    uint32_t accL[MI][4][2];
#pragma unroll
    for (int mi = 0; mi < MI; mi++)
#pragma unroll
        for (int ni = 0; ni < 4; ni++) {
#pragma unroll
            for (int r = 0; r < 4; r++) acc[mi][ni][r] = 0.f;
            accL[mi][ni][0] = 0u; accL[mi][ni][1] = 0u;
        }

    uint32_t sbase[2][4];
#pragma unroll
    for (int b = 0; b < 2; b++) {
        __half* p = smbuf + b * BUF_E;
        sbase[b][0] = smem_u32(p);
        sbase[b][1] = smem_u32(p + ABUF_E);
        sbase[b][2] = smem_u32(p + 2 * ABUF_E);
        sbase[b][3] = smem_u32(p + 2 * ABUF_E + BBUF);
    }

    auto issue = [&](int k0, int buf) {
#pragma unroll
        for (int p = 0; p < 2; p++) {
            int id = t + p * 256;
            if (AROWS == 128 || p == 0) {
                int am = id >> 2, ac = (id & 3) * 8;
                size_t aoff = (size_t)(m0 + am) * K + k0 + ac;
                uint32_t ad = (uint32_t)(am * AS_STR + ac) * 2;
                CP16(sbase[buf][0] + ad, Ah + aoff);
                if (PASSES >= 2) CP16(sbase[buf][1] + ad, Al + aoff);
            }
            int bk = id >> 4, bc = (id & 15) * 8;
            size_t boff = (size_t)(k0 + bk) * N + n0 + bc;
            uint32_t bd = (uint32_t)(bk * BS_STR + bc) * 2;
            CP16(sbase[buf][2] + bd, Bh + boff);
            if (PASSES == 3) CP16(sbase[buf][3] + bd, Bl + boff);
        }
        CP_COMMIT();
    };

    issue(0, 0);
    const int nIter = K / 32;

    for (int it = 0; it < nIter; it++) {
        CP_WAIT0();
        __syncthreads();
        if (it + 1 < nIter) issue((it + 1) * 32, (it + 1) & 1);

        const int buf = it & 1;
        const uint32_t ah_s = sbase[buf][0];
        const uint32_t al_s = sbase[buf][1];
        const uint32_t bh_s = sbase[buf][2];
        const uint32_t bl_s = sbase[buf][3];

#pragma unroll
        for (int ks = 0; ks < 32; ks += 16) {
            uint32_t fah[MI][4], fal[MI][4], fbh[2][4], fbl[2][4];

            int arow = lane & 15;
            int acol = ks + ((lane >> 4) & 1) * 8;
#pragma unroll
            for (int mi = 0; mi < MI; mi++) {
                uint32_t off = (uint32_t)((wm * 16 * MI + mi * 16 + arow) * AS_STR + acol) * 2;
                LDSM4(fah[mi], ah_s + off);
                if (PASSES >= 2) LDSM4(fal[mi], al_s + off);
            }

            int bkrow = ks + (lane & 7) + ((lane >> 3) & 1) * 8;
#pragma unroll
            for (int np = 0; np < 2; np++) {
                int bcol = wn * 32 + np * 16 + ((lane >> 4) & 1) * 8;
                uint32_t off = (uint32_t)(bkrow * BS_STR + bcol) * 2;
                LDSM4T(fbh[np], bh_s + off);
                if (PASSES == 3) LDSM4T(fbl[np], bl_s + off);
            }

#pragma unroll
            for (int mi = 0; mi < MI; mi++)
#pragma unroll
                for (int ni = 0; ni < 4; ni++) {
                    const uint32_t* bh2 = &fbh[ni >> 1][(ni & 1) * 2];
                    MMA_FP16(acc[mi][ni], fah[mi], bh2[0], bh2[1]);
                    if (PASSES >= 2) MMA_F16A(accL[mi][ni], fal[mi], bh2[0], bh2[1]);
                    if (PASSES == 3) {
                        const uint32_t* bl2 = &fbl[ni >> 1][(ni & 1) * 2];
                        MMA_F16A(accL[mi][ni], fah[mi], bl2[0], bl2[1]);
                    }
                }
        }
        __syncthreads();
    }

    int g  = lane >> 2;
    int c2 = (lane & 3) * 2;
#pragma unroll
    for (int mi = 0; mi < MI; mi++)
#pragma unroll
        for (int ni = 0; ni < 4; ni++) {
            if (PASSES >= 2) {
                add_h2(&acc[mi][ni][0], accL[mi][ni][0]);
                add_h2(&acc[mi][ni][2], accL[mi][ni][1]);
            }
            int row = m0 + wm * 16 * MI + mi * 16 + g;
            int col = n0 + wn * 32 + ni * 8 + c2;
            *(float2*)(C + (size_t)row * N + col)       = make_float2(acc[mi][ni][0], acc[mi][ni][1]);
            *(float2*)(C + (size_t)(row + 8) * N + col) = make_float2(acc[mi][ni][2], acc[mi][ni][3]);
        }
}

#define GEMM64_BUF_E (2 * (64 * AS_STR) + 2 * BBUF)
#define GEMM64_SMEM  (2 * GEMM64_BUF_E * 2)

// fused QKV projection — q,k 3-pass; v 1-pass (linear path)
__global__ __launch_bounds__(256) void gemm_qkv_kernel(
    const __half* __restrict__ Ah, const __half* __restrict__ Al,
    const __half* __restrict__ wqh, const __half* __restrict__ wql,
    const __half* __restrict__ wkh, const __half* __restrict__ wkl,
    const __half* __restrict__ wvh,
    float* __restrict__ gq, float* __restrict__ gk, float* __restrict__ gv)
{
    extern __shared__ __half smbuf[];
    const int bx = blockIdx.x;
    const int m0 = blockIdx.y * 64;
    if (bx < 16)
        gemm_body<3, 2>(Ah, Al, wqh, wql, gq, QN, HID, m0, bx * 128, smbuf);
    else if (bx < 24)
        gemm_body<3, 2>(Ah, Al, wkh, wkl, gk, KVN, HID, m0, (bx - 16) * 128, smbuf);
    else
        gemm_body<1, 2>(Ah, Ah, wvh, wvh, gv, KVN, HID, m0, (bx - 24) * 128, smbuf);
}

// output projection — 1-pass (linear path)
__global__ __launch_bounds__(256) void gemm_wo_kernel(
    const __half* __restrict__ Ah,
    const __half* __restrict__ Bh, float* __restrict__ C)
{
    extern __shared__ __half smbuf[];
    gemm_body<1, 2>(Ah, Ah, Bh, Bh, C, HID, QN, blockIdx.y * 64, blockIdx.x * 128, smbuf);
}

// =====================================================================
// Fused RMSNorm (+weight) + RoPE — warp-per-head (unchanged)
// =====================================================================
__global__ __launch_bounds__(256) void norm_rope_kernel(
    const float* __restrict__ q, const float* __restrict__ k, const float* __restrict__ v,
    const float* __restrict__ cosp, const float* __restrict__ sinp,
    const float* __restrict__ qw, const float* __restrict__ kw,
    __half* __restrict__ qh, __half* __restrict__ ql,
    __half* __restrict__ kh, __half* __restrict__ kl,
    __half* __restrict__ vh)
{
    const int lane = threadIdx.x & 31;
    const int row  = blockIdx.x * 8 + (threadIdx.x >> 5);
    const int s    = row >> 4;
    const int idx  = row & 15;

    const float* base;
    const float* w;
    __half *oh, *ol;
    bool rope;
    if (idx < 8) {
        base = q + (size_t)s * QN + idx * DH; w = qw; rope = true;
        oh = qh + (size_t)s * QN + idx * DH; ol = ql + (size_t)s * QN + idx * DH;
    } else if (idx < 12) {
        base = k + (size_t)s * KVN + (idx - 8) * DH; w = kw; rope = true;
        oh = kh + (size_t)s * KVN + (idx - 8) * DH; ol = kl + (size_t)s * KVN + (idx - 8) * DH;
    } else {
        base = v + (size_t)s * KVN + (idx - 12) * DH; w = nullptr; rope = false;
        oh = vh + (size_t)s * KVN + (idx - 12) * DH; ol = nullptr;
    }

    const int d0 = lane * 8;
    float x[8];
    *(float4*)&x[0] = *(const float4*)(base + d0);
    *(float4*)&x[4] = *(const float4*)(base + d0 + 4);

    float ss = 0.f;
#pragma unroll
    for (int j = 0; j < 8; j++) ss += x[j] * x[j];
#pragma unroll
    for (int o = 16; o; o >>= 1) ss += __shfl_xor_sync(0xffffffffu, ss, o);

    float inv = rsqrtf(ss * (1.0f / 256.0f) + 1e-6f);
    float y[8];
#pragma unroll
    for (int j = 0; j < 8; j++) y[j] = x[j] * inv;
    if (w) {
        float wv[8];
        *(float4*)&wv[0] = *(const float4*)(w + d0);
        *(float4*)&wv[4] = *(const float4*)(w + d0 + 4);
#pragma unroll
        for (int j = 0; j < 8; j++) y[j] *= wv[j];
    }

    float out[8];
    if (rope) {
        float c[8], si[8];
        *(float4*)&c[0]  = *(const float4*)(cosp + (size_t)s * DH + d0);
        *(float4*)&c[4]  = *(const float4*)(cosp + (size_t)s * DH + d0 + 4);
        *(float4*)&si[0] = *(const float4*)(sinp + (size_t)s * DH + d0);
        *(float4*)&si[4] = *(const float4*)(sinp + (size_t)s * DH + d0 + 4);
#pragma unroll
        for (int j = 0; j < 8; j++) {
            float pv = __shfl_xor_sync(0xffffffffu, y[j], 16);
            float rh = (lane < 16) ? -pv : pv;
            out[j] = y[j] * c[j] + rh * si[j];
        }
    } else {
#pragma unroll
        for (int j = 0; j < 8; j++) out[j] = y[j];
    }

    __half hi8[8], lo8[8];
#pragma unroll
    for (int j = 0; j < 8; j++) {
        hi8[j] = __float2half_rn(out[j]);
        lo8[j] = __float2half_rn(out[j] - __half2float(hi8[j]));
    }
    *(uint4*)(oh + d0) = *(uint4*)hi8;
    if (ol) *(uint4*)(ol + d0) = *(uint4*)lo8;
}

// =====================================================================
// TC flash attention: 64-q tiles, 4 warps, 2 CTAs/SM.
// QK 3-pass; PV single-pass; output single fp16 (wo is 1-pass now).
// =====================================================================
#define ATT_SM_BYTES (2 * 64 * 512 + 3 * 32 * 512)   // 114688

__global__ __launch_bounds__(128, 2) void attn_tc_kernel(
    const __half* __restrict__ Qh, const __half* __restrict__ Ql,
    const __half* __restrict__ Kh, const __half* __restrict__ Kl,
    const __half* __restrict__ Vh,
    __half* __restrict__ Oh)
{
    extern __shared__ __half sm2[];
    const int t    = threadIdx.x;
    const int lane = t & 31;
    const int w    = t >> 5;
    const int q0   = blockIdx.x * 64;
    const int h    = blockIdx.y;
    const int kvh  = h >> 1;

    const uint32_t sQh = smem_u32(sm2);
    const uint32_t sQl = sQh + 64 * 512;
    const uint32_t sKh = sQl + 64 * 512;
    const uint32_t sKl = sKh + 32 * 512;
    const uint32_t sVh = sKl + 32 * 512;

    // ---- Q load ----
    const __half* gqh = Qh + (size_t)q0 * QN + h * DH;
    const __half* gql = Ql + (size_t)q0 * QN + h * DH;
#pragma unroll
    for (int it = 0; it < 16; it++) {
        int id = t + it * 128;
        int row = id >> 5, cb = id & 31;
        uint32_t d = swz(row, cb);
        size_t g = (size_t)row * QN + cb * 8;
        CP16(sQh + d, gqh + g);
        CP16(sQl + d, gql + g);
    }
    CP_COMMIT();

    auto issueKV = [&](int k0) {
        const __half* gkh = Kh + (size_t)k0 * KVN + kvh * DH;
        const __half* gkl = Kl + (size_t)k0 * KVN + kvh * DH;
        const __half* gvh = Vh + (size_t)k0 * KVN + kvh * DH;
#pragma unroll
        for (int it = 0; it < 8; it++) {
            int id = t + it * 128;
            int row = id >> 5, cb = id & 31;
            uint32_t d = swz(row, cb);
            size_t g = (size_t)row * KVN + cb * 8;
            CP16(sKh + d, gkh + g);
            CP16(sKl + d, gkl + g);
            CP16(sVh + d, gvh + g);
        }
        CP_COMMIT();
    };

    float o[32][4];
#pragma unroll
    for (int dt = 0; dt < 32; dt++)
#pragma unroll
        for (int r = 0; r < 4; r++) o[dt][r] = 0.f;
    float mrow[2] = {-1e30f, -1e30f};
    float lrow[2] = {0.f, 0.f};

    const int kb_lo = max(0, q0 - (WIN - 1)) >> 5;
    const int kb_hi = (q0 + 63) >> 5;
    const int qw_lo = q0 + w * 16;
    const int gq_row = lane >> 2;
    const int t4 = lane & 3;

    issueKV(kb_lo * 32);

    for (int kb = kb_lo; kb <= kb_hi; kb++) {
        CP_WAIT0();
        __syncthreads();

        const int k0 = kb * 32;
        bool active = (k0 <= qw_lo + 15) && (k0 + 31 >= qw_lo - (WIN - 1));
        if (active) {
            float s[4][4];
            uint32_t sl[4][2];
#pragma unroll
            for (int tl = 0; tl < 4; tl++) {
#pragma unroll
                for (int r = 0; r < 4; r++) s[tl][r] = 0.f;
                sl[tl][0] = 0u; sl[tl][1] = 0u;
            }

#pragma unroll
            for (int dc = 0; dc < 16; dc++) {
                uint32_t qa[4], qb[4], k1h[4], k2h[4], k1l[4], k2l[4];
                int cb = dc * 2 + (lane >> 4);
                uint32_t qoff = swz(w * 16 + (lane & 15), cb);
                LDSM4(qa, sQh + qoff);
                LDSM4(qb, sQl + qoff);
                uint32_t koff = swz(lane & 15, cb);
                LDSM4(k1h, sKh + koff);
                LDSM4(k2h, sKh + koff + 16 * 512);
                LDSM4(k1l, sKl + koff);
                LDSM4(k2l, sKl + koff + 16 * 512);

                MMA_FP16(s[0], qa, k1h[0], k1h[2]);
                MMA_FP16(s[1], qa, k1h[1], k1h[3]);
                MMA_FP16(s[2], qa, k2h[0], k2h[2]);
                MMA_FP16(s[3], qa, k2h[1], k2h[3]);
                MMA_F16A(sl[0], qa, k1l[0], k1l[2]);
                MMA_F16A(sl[1], qa, k1l[1], k1l[3]);
                MMA_F16A(sl[2], qa, k2l[0], k2l[2]);
                MMA_F16A(sl[3], qa, k2l[1], k2l[3]);
                MMA_F16A(sl[0], qb, k1h[0], k1h[2]);
                MMA_F16A(sl[1], qb, k1h[1], k1h[3]);
                MMA_F16A(sl[2], qb, k2h[0], k2h[2]);
                MMA_F16A(sl[3], qb, k2h[1], k2h[3]);
            }
#pragma unroll
            for (int tl = 0; tl < 4; tl++) {
                add_h2(&s[tl][0], sl[tl][0]);
                add_h2(&s[tl][2], sl[tl][1]);
            }

            float corr[2];
#pragma unroll
            for (int r = 0; r < 2; r++) {
                int qg = qw_lo + gq_row + r * 8;
                float mx = -1e30f;
#pragma unroll
                for (int tl = 0; tl < 4; tl++) {
#pragma unroll
                    for (int c = 0; c < 2; c++) {
                        int kg = k0 + tl * 8 + 2 * t4 + c;
                        bool ok = (kg <= qg) && (qg - kg < WIN);
                        if (!ok) s[tl][r * 2 + c] = -1e30f;
                        mx = fmaxf(mx, s[tl][r * 2 + c]);
                    }
                }
                mx = fmaxf(mx, __shfl_xor_sync(0xffffffffu, mx, 1));
                mx = fmaxf(mx, __shfl_xor_sync(0xffffffffu, mx, 2));
                float m_new = fmaxf(mrow[r], mx);
                float mexp = (m_new <= -1e29f) ? 0.f : m_new;
                float sum = 0.f;
#pragma unroll
                for (int tl = 0; tl < 4; tl++) {
#pragma unroll
                    for (int c = 0; c < 2; c++) {
                        float p = __expf(s[tl][r * 2 + c] - mexp);
                        s[tl][r * 2 + c] = p;
                        sum += p;
                    }
                }
                sum += __shfl_xor_sync(0xffffffffu, sum, 1);
                sum += __shfl_xor_sync(0xffffffffu, sum, 2);
                corr[r] = __expf(mrow[r] - m_new);
                mrow[r] = m_new;
                lrow[r] = lrow[r] * corr[r] + sum;
            }

            // P -> single fp16 A-fragments
            uint32_t ph[2][4];
#pragma unroll
            for (int kc = 0; kc < 2; kc++) {
#pragma unroll
                for (int r2 = 0; r2 < 4; r2++) {
                    int tl = kc * 2 + (r2 >> 1);
                    int r  = r2 & 1;
                    __half2 hh = __halves2half2(__float2half_rn(s[tl][r * 2 + 0]),
                                                __float2half_rn(s[tl][r * 2 + 1]));
                    ph[kc][r2] = *(uint32_t*)&hh;
                }
            }

#pragma unroll
            for (int dt = 0; dt < 32; dt++) {
                o[dt][0] *= corr[0]; o[dt][1] *= corr[0];
                o[dt][2] *= corr[1]; o[dt][3] *= corr[1];
            }

#pragma unroll
            for (int dg = 0; dg < 16; dg++) {
#pragma unroll
                for (int kc = 0; kc < 2; kc++) {
                    uint32_t vh4[4];
                    int row_v = kc * 16 + (lane & 7) + ((lane >> 3) & 1) * 8;
                    int cb_v  = dg * 2 + ((lane >> 4) & 1);
                    LDSM4T(vh4, sVh + swz(row_v, cb_v));
                    MMA_FP16(o[2 * dg],     ph[kc], vh4[0], vh4[1]);
                    MMA_FP16(o[2 * dg + 1], ph[kc], vh4[2], vh4[3]);
                }
            }
        }
        __syncthreads();
        if (kb < kb_hi) issueKV((kb + 1) * 32);
    }

    // finalize -> single fp16 output (wo GEMM is 1-pass)
    float inv0 = 1.f / lrow[0];
    float inv1 = 1.f / lrow[1];
    size_t r0 = (size_t)(q0 + w * 16 + gq_row) * QN + h * DH;
    size_t r1 = r0 + (size_t)8 * QN;
#pragma unroll
    for (int dt = 0; dt < 32; dt++) {
        int col = dt * 8 + 2 * t4;
        *(__half2*)(Oh + r0 + col) = __halves2half2(
            __float2half_rn(o[dt][0] * inv0), __float2half_rn(o[dt][1] * inv0));
        *(__half2*)(Oh + r1 + col) = __halves2half2(
            __float2half_rn(o[dt][2] * inv1), __float2half_rn(o[dt][3] * inv1));
    }
}

// =====================================================================
// kernel_launch
// =====================================================================
extern "C" void kernel_launch(void* const* d_in, const int* in_sizes, int n_in,
                              void* d_out, int out_size)
{
    const float* hs   = (const float*)d_in[0];
    const float* cosp = (const float*)d_in[1];
    const float* sinp = (const float*)d_in[2];
    const float* wq   = (const float*)d_in[3];
    const float* wk   = (const float*)d_in[4];
    const float* wv   = (const float*)d_in[5];
    const float* wo   = (const float*)d_in[6];
    const float* qw   = (const float*)d_in[7];
    const float* kw   = (const float*)d_in[8];
    float* out = (float*)d_out;

    float *gq, *gk, *gv;
    cudaGetSymbolAddress((void**)&gq, g_q);
    cudaGetSymbolAddress((void**)&gk, g_k);
    cudaGetSymbolAddress((void**)&gv, g_v);

    __half *hsh, *hsl, *wqh, *wql, *wkh, *wkl, *wvh, *woh, *ath;
    __half *qh, *ql, *kh, *kl, *vh;
    cudaGetSymbolAddress((void**)&hsh, g_hs_h); cudaGetSymbolAddress((void**)&hsl, g_hs_l);
    cudaGetSymbolAddress((void**)&wqh, g_wq_h); cudaGetSymbolAddress((void**)&wql, g_wq_l);
    cudaGetSymbolAddress((void**)&wkh, g_wk_h); cudaGetSymbolAddress((void**)&wkl, g_wk_l);
    cudaGetSymbolAddress((void**)&wvh, g_wv_h);
    cudaGetSymbolAddress((void**)&woh, g_wo_h);
    cudaGetSymbolAddress((void**)&ath, g_at_h);
    cudaGetSymbolAddress((void**)&qh, g_qh);    cudaGetSymbolAddress((void**)&ql, g_ql);
    cudaGetSymbolAddress((void**)&kh, g_kh);    cudaGetSymbolAddress((void**)&kl, g_kl);
    cudaGetSymbolAddress((void**)&vh, g_vh);

    cudaFuncSetAttribute(gemm_qkv_kernel, cudaFuncAttributeMaxDynamicSharedMemorySize,
                         GEMM64_SMEM);
    cudaFuncSetAttribute(gemm_wo_kernel, cudaFuncAttributeMaxDynamicSharedMemorySize,
                         GEMM64_SMEM);
    cudaFuncSetAttribute(attn_tc_kernel, cudaFuncAttributeMaxDynamicSharedMemorySize,
                         ATT_SM_BYTES);

    // all splits in one launch
    split_all_kernel<<<20480, 256>>>(hs, wq, wk, wv, wo,
                                     hsh, hsl, wqh, wql, wkh, wkl, wvh, woh);

    // fused QKV projections (q,k 3-pass; v 1-pass)
    gemm_qkv_kernel<<<dim3(32, S / 64), 256, GEMM64_SMEM>>>(
        hsh, hsl, wqh, wql, wkh, wkl, wvh, gq, gk, gv);

    // RMSNorm + RoPE
    norm_rope_kernel<<<S * 16 / 8, 256>>>(gq, gk, gv, cosp, sinp, qw, kw,
                                          qh, ql, kh, kl, vh);

    // attention (PV single-pass, single fp16 output)
    attn_tc_kernel<<<dim3(S / 64, NH), 128, ATT_SM_BYTES>>>(
        qh, ql, kh, kl, vh, ath);

    // output projection — 1-pass
    gemm_wo_kernel<<<dim3(HID / 128, S / 64), 256, GEMM64_SMEM>>>(
        ath, woh, out);
}

// round 13
// speedup vs baseline: 4.5592x; 1.0181x over previous
#include <cuda_runtime.h>
#include <cuda_fp16.h>
#include <math.h>
#include <stdint.h>

// ---------------- problem constants ----------------
#define S     2048
#define HID   2560
#define NH    8
#define NKV   4
#define DH    256
#define WIN   1024
#define QN    (NH*DH)    // 2048
#define KVN   (NKV*DH)   // 1024

// ---------------- scratch ----------------
__device__ float g_q[S * QN];
__device__ float g_k[S * KVN];
__device__ float g_v[S * KVN];

__device__ __half g_hs_h[S * HID],  g_hs_l[S * HID];
__device__ __half g_wq_h[HID * QN], g_wq_l[HID * QN];
__device__ __half g_wk_h[HID * KVN];
__device__ __half g_wv_h[HID * KVN];
__device__ __half g_wo_h[QN * HID];
__device__ __half g_at_h[S * QN];

__device__ __half g_qh[S * QN],  g_ql[S * QN];
__device__ __half g_kh[S * KVN], g_kl[S * KVN];
__device__ __half g_vh[S * KVN];

// ---------------- PTX helpers ----------------
#define CP16(dst_u32, src_ptr) \
    asm volatile("cp.async.cg.shared.global [%0], [%1], 16;\n" :: "r"(dst_u32), "l"(src_ptr))
#define CP_COMMIT()  asm volatile("cp.async.commit_group;\n")
#define CP_WAIT0()   asm volatile("cp.async.wait_group 0;\n" ::: "memory")

#define LDSM4(R, addr) \
    asm volatile("ldmatrix.sync.aligned.m8n8.x4.shared.b16 {%0,%1,%2,%3}, [%4];\n" \
        : "=r"((R)[0]), "=r"((R)[1]), "=r"((R)[2]), "=r"((R)[3]) : "r"(addr))
#define LDSM4T(R, addr) \
    asm volatile("ldmatrix.sync.aligned.m8n8.x4.trans.shared.b16 {%0,%1,%2,%3}, [%4];\n" \
        : "=r"((R)[0]), "=r"((R)[1]), "=r"((R)[2]), "=r"((R)[3]) : "r"(addr))

#define MMA_FP16(d, a, b0, b1) \
    asm volatile("mma.sync.aligned.m16n8k16.row.col.f32.f16.f16.f32 " \
        "{%0,%1,%2,%3},{%4,%5,%6,%7},{%8,%9},{%0,%1,%2,%3};\n" \
        : "+f"((d)[0]), "+f"((d)[1]), "+f"((d)[2]), "+f"((d)[3]) \
        : "r"((a)[0]), "r"((a)[1]), "r"((a)[2]), "r"((a)[3]), "r"(b0), "r"(b1))

#define MMA_F16A(d, a, b0, b1) \
    asm volatile("mma.sync.aligned.m16n8k16.row.col.f16.f16.f16.f16 " \
        "{%0,%1},{%2,%3,%4,%5},{%6,%7},{%0,%1};\n" \
        : "+r"((d)[0]), "+r"((d)[1]) \
        : "r"((a)[0]), "r"((a)[1]), "r"((a)[2]), "r"((a)[3]), "r"(b0), "r"(b1))

__device__ __forceinline__ uint32_t smem_u32(const void* p) {
    return (uint32_t)__cvta_generic_to_shared(p);
}
__device__ __forceinline__ void add_h2(float* f01, uint32_t packed) {
    __half2 h = *(__half2*)&packed;
    float2 v = __half22float2(h);
    f01[0] += v.x; f01[1] += v.y;
}
// XOR swizzle for 512B rows
__device__ __forceinline__ uint32_t swz(int row, int cb) {
    return (uint32_t)(row * 512 + ((cb ^ (row & 7)) << 4));
}

// =====================================================================
// Fused split kernel (one launch). wk/wv/wo: hi only now.
// blocks: [0,5120) hs | [5120,10240) wq | [10240,12800) wk (hi)
//         [12800,15360) wv (hi) | [15360,20480) wo (hi)
// =====================================================================
__global__ __launch_bounds__(256) void split_all_kernel(
    const float* __restrict__ hs, const float* __restrict__ wq,
    const float* __restrict__ wk, const float* __restrict__ wv,
    const float* __restrict__ wo,
    __half* __restrict__ hsh, __half* __restrict__ hsl,
    __half* __restrict__ wqh, __half* __restrict__ wql,
    __half* __restrict__ wkh, __half* __restrict__ wvh,
    __half* __restrict__ woh)
{
    int b = blockIdx.x;
    const float* x; __half *h, *l;
    if (b < 5120)       { x = hs; h = hsh; l = hsl; }
    else if (b < 10240) { x = wq; h = wqh; l = wql; b -= 5120; }
    else if (b < 12800) { x = wk; h = wkh; l = nullptr; b -= 10240; }
    else if (b < 15360) { x = wv; h = wvh; l = nullptr; b -= 12800; }
    else                { x = wo; h = woh; l = nullptr; b -= 15360; }

    int i = (b * 256 + threadIdx.x) * 4;
    float4 v = *(const float4*)(x + i);
    __half h0 = __float2half_rn(v.x), h1 = __float2half_rn(v.y);
    __half h2 = __float2half_rn(v.z), h3 = __float2half_rn(v.w);
    *(__half2*)(h + i)     = __halves2half2(h0, h1);
    *(__half2*)(h + i + 2) = __halves2half2(h2, h3);
    if (l) {
        *(__half2*)(l + i)     = __halves2half2(
            __float2half_rn(v.x - __half2float(h0)), __float2half_rn(v.y - __half2float(h1)));
        *(__half2*)(l + i + 2) = __halves2half2(
            __float2half_rn(v.z - __half2float(h2)), __float2half_rn(v.w - __half2float(h3)));
    }
}

// =====================================================================
// fp16 TC GEMM body — PASSES/MI compile-time.
//  PASSES=1: C = Ah*Bh (f32acc)
//  PASSES=2: += Al*Bh (f16acc)
//  PASSES=3: += Ah*Bl (f16acc)
// =====================================================================
#define AS_STR 40
#define BS_STR 136
#define BBUF   (32 * BS_STR)

template <int PASSES, int MI>
__device__ __forceinline__ void gemm_body(
    const __half* __restrict__ Ah, const __half* __restrict__ Al,
    const __half* __restrict__ Bh, const __half* __restrict__ Bl,
    float* __restrict__ C, int N, int K, int m0, int n0,
    __half* smbuf)
{
    constexpr int AROWS  = MI * 32;
    constexpr int ABUF_E = AROWS * AS_STR;
    constexpr int BUF_E  = 2 * ABUF_E + 2 * BBUF;

    const int t    = threadIdx.x;
    const int lane = t & 31;
    const int wid  = t >> 5;
    const int wm   = wid >> 2;
    const int wn   = wid & 3;

    float acc[MI][4][4];
    uint32_t accL[MI][4][2];
#pragma unroll
    for (int mi = 0; mi < MI; mi++)
#pragma unroll
        for (int ni = 0; ni < 4; ni++) {
#pragma unroll
            for (int r = 0; r < 4; r++) acc[mi][ni][r] = 0.f;
            accL[mi][ni][0] = 0u; accL[mi][ni][1] = 0u;
        }

    uint32_t sbase[2][4];
#pragma unroll
    for (int b = 0; b < 2; b++) {
        __half* p = smbuf + b * BUF_E;
        sbase[b][0] = smem_u32(p);
        sbase[b][1] = smem_u32(p + ABUF_E);
        sbase[b][2] = smem_u32(p + 2 * ABUF_E);
        sbase[b][3] = smem_u32(p + 2 * ABUF_E + BBUF);
    }

    auto issue = [&](int k0, int buf) {
#pragma unroll
        for (int p = 0; p < 2; p++) {
            int id = t + p * 256;
            if (AROWS == 128 || p == 0) {
                int am = id >> 2, ac = (id & 3) * 8;
                size_t aoff = (size_t)(m0 + am) * K + k0 + ac;
                uint32_t ad = (uint32_t)(am * AS_STR + ac) * 2;
                CP16(sbase[buf][0] + ad, Ah + aoff);
                if (PASSES >= 2) CP16(sbase[buf][1] + ad, Al + aoff);
            }
            int bk = id >> 4, bc = (id & 15) * 8;
            size_t boff = (size_t)(k0 + bk) * N + n0 + bc;
            uint32_t bd = (uint32_t)(bk * BS_STR + bc) * 2;
            CP16(sbase[buf][2] + bd, Bh + boff);
            if (PASSES == 3) CP16(sbase[buf][3] + bd, Bl + boff);
        }
        CP_COMMIT();
    };

    issue(0, 0);
    const int nIter = K / 32;

    for (int it = 0; it < nIter; it++) {
        CP_WAIT0();
        __syncthreads();
        if (it + 1 < nIter) issue((it + 1) * 32, (it + 1) & 1);

        const int buf = it & 1;
        const uint32_t ah_s = sbase[buf][0];
        const uint32_t al_s = sbase[buf][1];
        const uint32_t bh_s = sbase[buf][2];
        const uint32_t bl_s = sbase[buf][3];

#pragma unroll
        for (int ks = 0; ks < 32; ks += 16) {
            uint32_t fah[MI][4], fal[MI][4], fbh[2][4], fbl[2][4];

            int arow = lane & 15;
            int acol = ks + ((lane >> 4) & 1) * 8;
#pragma unroll
            for (int mi = 0; mi < MI; mi++) {
                uint32_t off = (uint32_t)((wm * 16 * MI + mi * 16 + arow) * AS_STR + acol) * 2;
                LDSM4(fah[mi], ah_s + off);
                if (PASSES >= 2) LDSM4(fal[mi], al_s + off);
            }

            int bkrow = ks + (lane & 7) + ((lane >> 3) & 1) * 8;
#pragma unroll
            for (int np = 0; np < 2; np++) {
                int bcol = wn * 32 + np * 16 + ((lane >> 4) & 1) * 8;
                uint32_t off = (uint32_t)(bkrow * BS_STR + bcol) * 2;
                LDSM4T(fbh[np], bh_s + off);
                if (PASSES == 3) LDSM4T(fbl[np], bl_s + off);
            }

#pragma unroll
            for (int mi = 0; mi < MI; mi++)
#pragma unroll
                for (int ni = 0; ni < 4; ni++) {
                    const uint32_t* bh2 = &fbh[ni >> 1][(ni & 1) * 2];
                    MMA_FP16(acc[mi][ni], fah[mi], bh2[0], bh2[1]);
                    if (PASSES >= 2) MMA_F16A(accL[mi][ni], fal[mi], bh2[0], bh2[1]);
                    if (PASSES == 3) {
                        const uint32_t* bl2 = &fbl[ni >> 1][(ni & 1) * 2];
                        MMA_F16A(accL[mi][ni], fah[mi], bl2[0], bl2[1]);
                    }
                }
        }
        __syncthreads();
    }

    int g  = lane >> 2;
    int c2 = (lane & 3) * 2;
#pragma unroll
    for (int mi = 0; mi < MI; mi++)
#pragma unroll
        for (int ni = 0; ni < 4; ni++) {
            if (PASSES >= 2) {
                add_h2(&acc[mi][ni][0], accL[mi][ni][0]);
                add_h2(&acc[mi][ni][2], accL[mi][ni][1]);
            }
            int row = m0 + wm * 16 * MI + mi * 16 + g;
            int col = n0 + wn * 32 + ni * 8 + c2;
            *(float2*)(C + (size_t)row * N + col)       = make_float2(acc[mi][ni][0], acc[mi][ni][1]);
            *(float2*)(C + (size_t)(row + 8) * N + col) = make_float2(acc[mi][ni][2], acc[mi][ni][3]);
        }
}

#define GEMM64_BUF_E (2 * (64 * AS_STR) + 2 * BBUF)
#define GEMM64_SMEM  (2 * GEMM64_BUF_E * 2)

// fused QKV projection — q 3-pass; k 2-pass (weight-lo dropped); v 1-pass
__global__ __launch_bounds__(256) void gemm_qkv_kernel(
    const __half* __restrict__ Ah, const __half* __restrict__ Al,
    const __half* __restrict__ wqh, const __half* __restrict__ wql,
    const __half* __restrict__ wkh,
    const __half* __restrict__ wvh,
    float* __restrict__ gq, float* __restrict__ gk, float* __restrict__ gv)
{
    extern __shared__ __half smbuf[];
    const int bx = blockIdx.x;
    const int m0 = blockIdx.y * 64;
    if (bx < 16)
        gemm_body<3, 2>(Ah, Al, wqh, wql, gq, QN, HID, m0, bx * 128, smbuf);
    else if (bx < 24)
        gemm_body<2, 2>(Ah, Al, wkh, wkh, gk, KVN, HID, m0, (bx - 16) * 128, smbuf);
    else
        gemm_body<1, 2>(Ah, Ah, wvh, wvh, gv, KVN, HID, m0, (bx - 24) * 128, smbuf);
}

// output projection — 1-pass (linear path)
__global__ __launch_bounds__(256) void gemm_wo_kernel(
    const __half* __restrict__ Ah,
    const __half* __restrict__ Bh, float* __restrict__ C)
{
    extern __shared__ __half smbuf[];
    gemm_body<1, 2>(Ah, Ah, Bh, Bh, C, HID, QN, blockIdx.y * 64, blockIdx.x * 128, smbuf);
}

// =====================================================================
// Fused RMSNorm (+weight) + RoPE — warp-per-head (unchanged)
// =====================================================================
__global__ __launch_bounds__(256) void norm_rope_kernel(
    const float* __restrict__ q, const float* __restrict__ k, const float* __restrict__ v,
    const float* __restrict__ cosp, const float* __restrict__ sinp,
    const float* __restrict__ qw, const float* __restrict__ kw,
    __half* __restrict__ qh, __half* __restrict__ ql,
    __half* __restrict__ kh, __half* __restrict__ kl,
    __half* __restrict__ vh)
{
    const int lane = threadIdx.x & 31;
    const int row  = blockIdx.x * 8 + (threadIdx.x >> 5);
    const int s    = row >> 4;
    const int idx  = row & 15;

    const float* base;
    const float* w;
    __half *oh, *ol;
    bool rope;
    if (idx < 8) {
        base = q + (size_t)s * QN + idx * DH; w = qw; rope = true;
        oh = qh + (size_t)s * QN + idx * DH; ol = ql + (size_t)s * QN + idx * DH;
    } else if (idx < 12) {
        base = k + (size_t)s * KVN + (idx - 8) * DH; w = kw; rope = true;
        oh = kh + (size_t)s * KVN + (idx - 8) * DH; ol = kl + (size_t)s * KVN + (idx - 8) * DH;
    } else {
        base = v + (size_t)s * KVN + (idx - 12) * DH; w = nullptr; rope = false;
        oh = vh + (size_t)s * KVN + (idx - 12) * DH; ol = nullptr;
    }

    const int d0 = lane * 8;
    float x[8];
    *(float4*)&x[0] = *(const float4*)(base + d0);
    *(float4*)&x[4] = *(const float4*)(base + d0 + 4);

    float ss = 0.f;
#pragma unroll
    for (int j = 0; j < 8; j++) ss += x[j] * x[j];
#pragma unroll
    for (int o = 16; o; o >>= 1) ss += __shfl_xor_sync(0xffffffffu, ss, o);

    float inv = rsqrtf(ss * (1.0f / 256.0f) + 1e-6f);
    float y[8];
#pragma unroll
    for (int j = 0; j < 8; j++) y[j] = x[j] * inv;
    if (w) {
        float wv[8];
        *(float4*)&wv[0] = *(const float4*)(w + d0);
        *(float4*)&wv[4] = *(const float4*)(w + d0 + 4);
#pragma unroll
        for (int j = 0; j < 8; j++) y[j] *= wv[j];
    }

    float out[8];
    if (rope) {
        float c[8], si[8];
        *(float4*)&c[0]  = *(const float4*)(cosp + (size_t)s * DH + d0);
        *(float4*)&c[4]  = *(const float4*)(cosp + (size_t)s * DH + d0 + 4);
        *(float4*)&si[0] = *(const float4*)(sinp + (size_t)s * DH + d0);
        *(float4*)&si[4] = *(const float4*)(sinp + (size_t)s * DH + d0 + 4);
#pragma unroll
        for (int j = 0; j < 8; j++) {
            float pv = __shfl_xor_sync(0xffffffffu, y[j], 16);
            float rh = (lane < 16) ? -pv : pv;
            out[j] = y[j] * c[j] + rh * si[j];
        }
    } else {
#pragma unroll
        for (int j = 0; j < 8; j++) out[j] = y[j];
    }

    __half hi8[8], lo8[8];
#pragma unroll
    for (int j = 0; j < 8; j++) {
        hi8[j] = __float2half_rn(out[j]);
        lo8[j] = __float2half_rn(out[j] - __half2float(hi8[j]));
    }
    *(uint4*)(oh + d0) = *(uint4*)hi8;
    if (ol) *(uint4*)(ol + d0) = *(uint4*)lo8;
}

// =====================================================================
// TC flash attention: 64-q tiles, 4 warps, 2 CTAs/SM.
// QK 3-pass; PV single-pass; interior keyblocks skip masking.
// =====================================================================
#define ATT_SM_BYTES (2 * 64 * 512 + 3 * 32 * 512)   // 114688

__global__ __launch_bounds__(128, 2) void attn_tc_kernel(
    const __half* __restrict__ Qh, const __half* __restrict__ Ql,
    const __half* __restrict__ Kh, const __half* __restrict__ Kl,
    const __half* __restrict__ Vh,
    __half* __restrict__ Oh)
{
    extern __shared__ __half sm2[];
    const int t    = threadIdx.x;
    const int lane = t & 31;
    const int w    = t >> 5;
    const int q0   = blockIdx.x * 64;
    const int h    = blockIdx.y;
    const int kvh  = h >> 1;

    const uint32_t sQh = smem_u32(sm2);
    const uint32_t sQl = sQh + 64 * 512;
    const uint32_t sKh = sQl + 64 * 512;
    const uint32_t sKl = sKh + 32 * 512;
    const uint32_t sVh = sKl + 32 * 512;

    // ---- Q load ----
    const __half* gqh = Qh + (size_t)q0 * QN + h * DH;
    const __half* gql = Ql + (size_t)q0 * QN + h * DH;
#pragma unroll
    for (int it = 0; it < 16; it++) {
        int id = t + it * 128;
        int row = id >> 5, cb = id & 31;
        uint32_t d = swz(row, cb);
        size_t g = (size_t)row * QN + cb * 8;
        CP16(sQh + d, gqh + g);
        CP16(sQl + d, gql + g);
    }
    CP_COMMIT();

    auto issueKV = [&](int k0) {
        const __half* gkh = Kh + (size_t)k0 * KVN + kvh * DH;
        const __half* gkl = Kl + (size_t)k0 * KVN + kvh * DH;
        const __half* gvh = Vh + (size_t)k0 * KVN + kvh * DH;
#pragma unroll
        for (int it = 0; it < 8; it++) {
            int id = t + it * 128;
            int row = id >> 5, cb = id & 31;
            uint32_t d = swz(row, cb);
            size_t g = (size_t)row * KVN + cb * 8;
            CP16(sKh + d, gkh + g);
            CP16(sKl + d, gkl + g);
            CP16(sVh + d, gvh + g);
        }
        CP_COMMIT();
    };

    float o[32][4];
#pragma unroll
    for (int dt = 0; dt < 32; dt++)
#pragma unroll
        for (int r = 0; r < 4; r++) o[dt][r] = 0.f;
    float mrow[2] = {-1e30f, -1e30f};
    float lrow[2] = {0.f, 0.f};

    const int kb_lo = max(0, q0 - (WIN - 1)) >> 5;
    const int kb_hi = (q0 + 63) >> 5;
    const int qw_lo = q0 + w * 16;
    const int gq_row = lane >> 2;
    const int t4 = lane & 3;

    issueKV(kb_lo * 32);

    for (int kb = kb_lo; kb <= kb_hi; kb++) {
        CP_WAIT0();
        __syncthreads();

        const int k0 = kb * 32;
        bool active = (k0 <= qw_lo + 15) && (k0 + 31 >= qw_lo - (WIN - 1));
        if (active) {
            // warp-uniform: every (qg,kg) pair in this warp's tile is unmasked
            bool interior = (k0 + 31 <= qw_lo) && (k0 >= qw_lo + 16 - WIN);

            float s[4][4];
            uint32_t sl[4][2];
#pragma unroll
            for (int tl = 0; tl < 4; tl++) {
#pragma unroll
                for (int r = 0; r < 4; r++) s[tl][r] = 0.f;
                sl[tl][0] = 0u; sl[tl][1] = 0u;
            }

#pragma unroll
            for (int dc = 0; dc < 16; dc++) {
                uint32_t qa[4], qb[4], k1h[4], k2h[4], k1l[4], k2l[4];
                int cb = dc * 2 + (lane >> 4);
                uint32_t qoff = swz(w * 16 + (lane & 15), cb);
                LDSM4(qa, sQh + qoff);
                LDSM4(qb, sQl + qoff);
                uint32_t koff = swz(lane & 15, cb);
                LDSM4(k1h, sKh + koff);
                LDSM4(k2h, sKh + koff + 16 * 512);
                LDSM4(k1l, sKl + koff);
                LDSM4(k2l, sKl + koff + 16 * 512);

                MMA_FP16(s[0], qa, k1h[0], k1h[2]);
                MMA_FP16(s[1], qa, k1h[1], k1h[3]);
                MMA_FP16(s[2], qa, k2h[0], k2h[2]);
                MMA_FP16(s[3], qa, k2h[1], k2h[3]);
                MMA_F16A(sl[0], qa, k1l[0], k1l[2]);
                MMA_F16A(sl[1], qa, k1l[1], k1l[3]);
                MMA_F16A(sl[2], qa, k2l[0], k2l[2]);
                MMA_F16A(sl[3], qa, k2l[1], k2l[3]);
                MMA_F16A(sl[0], qb, k1h[0], k1h[2]);
                MMA_F16A(sl[1], qb, k1h[1], k1h[3]);
                MMA_F16A(sl[2], qb, k2h[0], k2h[2]);
                MMA_F16A(sl[3], qb, k2h[1], k2h[3]);
            }
#pragma unroll
            for (int tl = 0; tl < 4; tl++) {
                add_h2(&s[tl][0], sl[tl][0]);
                add_h2(&s[tl][2], sl[tl][1]);
            }

            float corr[2];
#pragma unroll
            for (int r = 0; r < 2; r++) {
                float mx = -1e30f;
                if (interior) {
#pragma unroll
                    for (int tl = 0; tl < 4; tl++) {
                        mx = fmaxf(mx, fmaxf(s[tl][r * 2], s[tl][r * 2 + 1]));
                    }
                } else {
                    int qg = qw_lo + gq_row + r * 8;
#pragma unroll
                    for (int tl = 0; tl < 4; tl++) {
#pragma unroll
                        for (int c = 0; c < 2; c++) {
                            int kg = k0 + tl * 8 + 2 * t4 + c;
                            bool ok = (kg <= qg) && (qg - kg < WIN);
                            if (!ok) s[tl][r * 2 + c] = -1e30f;
                            mx = fmaxf(mx, s[tl][r * 2 + c]);
                        }
                    }
                }
                mx = fmaxf(mx, __shfl_xor_sync(0xffffffffu, mx, 1));
                mx = fmaxf(mx, __shfl_xor_sync(0xffffffffu, mx, 2));
                float m_new = fmaxf(mrow[r], mx);
                float mexp = (m_new <= -1e29f) ? 0.f : m_new;
                float sum = 0.f;
#pragma unroll
                for (int tl = 0; tl < 4; tl++) {
#pragma unroll
                    for (int c = 0; c < 2; c++) {
                        float p = __expf(s[tl][r * 2 + c] - mexp);
                        s[tl][r * 2 + c] = p;
                        sum += p;
                    }
                }
                sum += __shfl_xor_sync(0xffffffffu, sum, 1);
                sum += __shfl_xor_sync(0xffffffffu, sum, 2);
                corr[r] = __expf(mrow[r] - m_new);
                mrow[r] = m_new;
                lrow[r] = lrow[r] * corr[r] + sum;
            }

            // P -> single fp16 A-fragments
            uint32_t ph[2][4];
#pragma unroll
            for (int kc = 0; kc < 2; kc++) {
#pragma unroll
                for (int r2 = 0; r2 < 4; r2++) {
                    int tl = kc * 2 + (r2 >> 1);
                    int r  = r2 & 1;
                    __half2 hh = __halves2half2(__float2half_rn(s[tl][r * 2 + 0]),
                                                __float2half_rn(s[tl][r * 2 + 1]));
                    ph[kc][r2] = *(uint32_t*)&hh;
                }
            }

#pragma unroll
            for (int dt = 0; dt < 32; dt++) {
                o[dt][0] *= corr[0]; o[dt][1] *= corr[0];
                o[dt][2] *= corr[1]; o[dt][3] *= corr[1];
            }

#pragma unroll
            for (int dg = 0; dg < 16; dg++) {
#pragma unroll
                for (int kc = 0; kc < 2; kc++) {
                    uint32_t vh4[4];
                    int row_v = kc * 16 + (lane & 7) + ((lane >> 3) & 1) * 8;
                    int cb_v  = dg * 2 + ((lane >> 4) & 1);
                    LDSM4T(vh4, sVh + swz(row_v, cb_v));
                    MMA_FP16(o[2 * dg],     ph[kc], vh4[0], vh4[1]);
                    MMA_FP16(o[2 * dg + 1], ph[kc], vh4[2], vh4[3]);
                }
            }
        }
        __syncthreads();
        if (kb < kb_hi) issueKV((kb + 1) * 32);
    }

    // finalize -> single fp16 output (wo GEMM is 1-pass)
    float inv0 = 1.f / lrow[0];
    float inv1 = 1.f / lrow[1];
    size_t r0 = (size_t)(q0 + w * 16 + gq_row) * QN + h * DH;
    size_t r1 = r0 + (size_t)8 * QN;
#pragma unroll
    for (int dt = 0; dt < 32; dt++) {
        int col = dt * 8 + 2 * t4;
        *(__half2*)(Oh + r0 + col) = __halves2half2(
            __float2half_rn(o[dt][0] * inv0), __float2half_rn(o[dt][1] * inv0));
        *(__half2*)(Oh + r1 + col) = __halves2half2(
            __float2half_rn(o[dt][2] * inv1), __float2half_rn(o[dt][3] * inv1));
    }
}

// =====================================================================
// kernel_launch
// =====================================================================
extern "C" void kernel_launch(void* const* d_in, const int* in_sizes, int n_in,
                              void* d_out, int out_size)
{
    const float* hs   = (const float*)d_in[0];
    const float* cosp = (const float*)d_in[1];
    const float* sinp = (const float*)d_in[2];
    const float* wq   = (const float*)d_in[3];
    const float* wk   = (const float*)d_in[4];
    const float* wv   = (const float*)d_in[5];
    const float* wo   = (const float*)d_in[6];
    const float* qw   = (const float*)d_in[7];
    const float* kw   = (const float*)d_in[8];
    float* out = (float*)d_out;

    float *gq, *gk, *gv;
    cudaGetSymbolAddress((void**)&gq, g_q);
    cudaGetSymbolAddress((void**)&gk, g_k);
    cudaGetSymbolAddress((void**)&gv, g_v);

    __half *hsh, *hsl, *wqh, *wql, *wkh, *wvh, *woh, *ath;
    __half *qh, *ql, *kh, *kl, *vh;
    cudaGetSymbolAddress((void**)&hsh, g_hs_h); cudaGetSymbolAddress((void**)&hsl, g_hs_l);
    cudaGetSymbolAddress((void**)&wqh, g_wq_h); cudaGetSymbolAddress((void**)&wql, g_wq_l);
    cudaGetSymbolAddress((void**)&wkh, g_wk_h);
    cudaGetSymbolAddress((void**)&wvh, g_wv_h);
    cudaGetSymbolAddress((void**)&woh, g_wo_h);
    cudaGetSymbolAddress((void**)&ath, g_at_h);
    cudaGetSymbolAddress((void**)&qh, g_qh);    cudaGetSymbolAddress((void**)&ql, g_ql);
    cudaGetSymbolAddress((void**)&kh, g_kh);    cudaGetSymbolAddress((void**)&kl, g_kl);
    cudaGetSymbolAddress((void**)&vh, g_vh);

    cudaFuncSetAttribute(gemm_qkv_kernel, cudaFuncAttributeMaxDynamicSharedMemorySize,
                         GEMM64_SMEM);
    cudaFuncSetAttribute(gemm_wo_kernel, cudaFuncAttributeMaxDynamicSharedMemorySize,
                         GEMM64_SMEM);
    cudaFuncSetAttribute(attn_tc_kernel, cudaFuncAttributeMaxDynamicSharedMemorySize,
                         ATT_SM_BYTES);

    // all splits in one launch (wk/wv/wo hi-only)
    split_all_kernel<<<20480, 256>>>(hs, wq, wk, wv, wo,
                                     hsh, hsl, wqh, wql, wkh, wvh, woh);

    // fused QKV projections (q 3-pass; k 2-pass; v 1-pass)
    gemm_qkv_kernel<<<dim3(32, S / 64), 256, GEMM64_SMEM>>>(
        hsh, hsl, wqh, wql, wkh, wvh, gq, gk, gv);

    // RMSNorm + RoPE
    norm_rope_kernel<<<S * 16 / 8, 256>>>(gq, gk, gv, cosp, sinp, qw, kw,
                                          qh, ql, kh, kl, vh);

    // attention (PV single-pass, interior fast-path)
    attn_tc_kernel<<<dim3(S / 64, NH), 128, ATT_SM_BYTES>>>(
        qh, ql, kh, kl, vh, ath);

    // output projection — 1-pass
    gemm_wo_kernel<<<dim3(HID / 128, S / 64), 256, GEMM64_SMEM>>>(
        ath, woh, out);
}